// round 4
// baseline (speedup 1.0000x reference)
#include <cuda_runtime.h>
#include <mma.h>
#include <cstdint>

using namespace nvcuda;

// Problem constants
#define BB   4
#define TT   2048
#define CC   1024
#define NH   16
#define HD   64
#define MTOT (BB * TT)        // 8192

// Scratch (device globals: no runtime allocation allowed)
__device__ float g_Q[BB * TT * CC];
__device__ float g_K[BB * TT * CC];
__device__ float g_V[BB * TT * CC];
__device__ float g_Y[BB * TT * CC];

__device__ __forceinline__ uint32_t smem_u32(const void* p) {
    uint32_t a;
    asm("{ .reg .u64 t; cvta.to.shared.u64 t, %1; cvt.u32.u64 %0, t; }"
        : "=r"(a) : "l"(p));
    return a;
}
__device__ __forceinline__ void cp_async16(uint32_t dst, const void* src) {
    asm volatile("cp.async.cg.shared.global [%0], [%1], 16;"
                 :: "r"(dst), "l"(src) : "memory");
}

// ---------------------------------------------------------------------------
// WMMA tf32 GEMM (NT): C[M,N] = A[M,K] @ B[N,K]^T  (both K-contiguous fp32)
// CTA tile 128x128, BK=32, 256 threads (8 warps as 4x2 -> 32x64 per warp),
// cp.async double-buffered smem, in-fragment rna tf32 rounding.
// ---------------------------------------------------------------------------
#define GBM 128
#define GBN 128
#define GBK 32
#define SLD 36                       // smem row stride (floats), 16B aligned
#define ASTAGE (GBM * SLD)           // floats per A stage
#define GSM_FLOATS (4 * ASTAGE)      // A0,A1,B0,B1
#define GSM_BYTES  (GSM_FLOATS * 4)  // 73728

__global__ __launch_bounds__(256) void gemm_wmma_tf32(const float* __restrict__ A,
                                                      const float* __restrict__ Bm,
                                                      float* __restrict__ Cm,
                                                      int M, int N, int K) {
    extern __shared__ float smf[];
    float* sA = smf;                   // [2][128][SLD]
    float* sB = smf + 2 * ASTAGE;      // [2][128][SLD]
    const uint32_t sAu = smem_u32(sA);
    const uint32_t sBu = smem_u32(sB);

    const int tid = threadIdx.x;
    const int wid = tid >> 5;
    const int wm  = wid >> 1;          // 0..3 -> 32-row slab
    const int wn  = wid & 1;           // 0..1 -> 64-col slab
    const int bm  = blockIdx.y * GBM;
    const int bn  = blockIdx.x * GBN;
    const int KT  = K / GBK;

    wmma::fragment<wmma::accumulator, 16, 16, 8, float> acc[2][4];
#pragma unroll
    for (int i = 0; i < 2; i++)
#pragma unroll
        for (int j = 0; j < 4; j++) wmma::fill_fragment(acc[i][j], 0.0f);

    auto load_stage = [&](int s, int kt) {
#pragma unroll
        for (int i = 0; i < 4; i++) {
            int c   = tid + i * 256;       // 0..1023
            int row = c >> 3;              // 0..127 (8 chunks of 16B per row)
            int c4  = (c & 7) * 4;         // float offset in row
            uint32_t so = (uint32_t)((s * ASTAGE + row * SLD + c4) * 4);
            cp_async16(sAu + so, A  + (size_t)(bm + row) * K + kt * GBK + c4);
            cp_async16(sBu + so, Bm + (size_t)(bn + row) * K + kt * GBK + c4);
        }
    };

    load_stage(0, 0);
    asm volatile("cp.async.commit_group;" ::: "memory");

    for (int kt = 0; kt < KT; kt++) {
        const int cur = kt & 1;
        if (kt + 1 < KT) load_stage(cur ^ 1, kt + 1);
        asm volatile("cp.async.commit_group;" ::: "memory");
        asm volatile("cp.async.wait_group 1;" ::: "memory");
        __syncthreads();

        const float* At = sA + cur * ASTAGE;
        const float* Bt = sB + cur * ASTAGE;

#pragma unroll
        for (int kk = 0; kk < GBK / 8; kk++) {
            wmma::fragment<wmma::matrix_a, 16, 16, 8, wmma::precision::tf32,
                           wmma::row_major> af[2];
            wmma::fragment<wmma::matrix_b, 16, 16, 8, wmma::precision::tf32,
                           wmma::col_major> bf[4];
#pragma unroll
            for (int i = 0; i < 2; i++) {
                wmma::load_matrix_sync(af[i],
                    At + (wm * 32 + i * 16) * SLD + kk * 8, SLD);
#pragma unroll
                for (int e = 0; e < af[i].num_elements; e++)
                    af[i].x[e] = wmma::__float_to_tf32(af[i].x[e]);
            }
#pragma unroll
            for (int j = 0; j < 4; j++) {
                wmma::load_matrix_sync(bf[j],
                    Bt + (wn * 64 + j * 16) * SLD + kk * 8, SLD);
#pragma unroll
                for (int e = 0; e < bf[j].num_elements; e++)
                    bf[j].x[e] = wmma::__float_to_tf32(bf[j].x[e]);
            }
#pragma unroll
            for (int i = 0; i < 2; i++)
#pragma unroll
                for (int j = 0; j < 4; j++)
                    wmma::mma_sync(acc[i][j], af[i], bf[j], acc[i][j]);
        }
        __syncthreads();
    }

#pragma unroll
    for (int i = 0; i < 2; i++)
#pragma unroll
        for (int j = 0; j < 4; j++) {
            int row = bm + wm * 32 + i * 16;
            int col = bn + wn * 64 + j * 16;
            wmma::store_matrix_sync(Cm + (size_t)row * N + col, acc[i][j], N,
                                    wmma::mem_row_major);
        }
}

// ---------------------------------------------------------------------------
// Flash attention (causal, fp32) — unchanged from R1 (passing, rel_err 6.5e-7)
// ---------------------------------------------------------------------------
#define FPAD 68

__global__ __launch_bounds__(256) void flash_attn(const float* __restrict__ Q,
                                                  const float* __restrict__ K,
                                                  const float* __restrict__ V,
                                                  float* __restrict__ Y) {
    extern __shared__ float sm[];
    float* QsT = sm;
    float* KsT = sm + 64 * FPAD;
    float* Vs  = sm + 2 * 64 * FPAD;
    float* PsT = KsT;

    const int qt  = blockIdx.x;
    const int h   = blockIdx.y;
    const int b   = blockIdx.z;
    const int tid = threadIdx.x;
    const int tx  = tid & 15;
    const int ty  = tid >> 4;

    const float* Qb = Q + ((size_t)b * TT + qt * 64) * CC + h * HD;
    const float* Kb = K + (size_t)b * TT * CC + h * HD;
    const float* Vb = V + (size_t)b * TT * CC + h * HD;

#pragma unroll
    for (int i = 0; i < 4; i++) {
        int idx = tid + i * 256;
        int row = idx >> 4;
        int d4  = (idx & 15) * 4;
        float4 v = *(const float4*)(Qb + (size_t)row * CC + d4);
        QsT[(d4 + 0) * FPAD + row] = v.x;
        QsT[(d4 + 1) * FPAD + row] = v.y;
        QsT[(d4 + 2) * FPAD + row] = v.z;
        QsT[(d4 + 3) * FPAD + row] = v.w;
    }

    float m_i[4], l_i[4], O[4][4];
#pragma unroll
    for (int i = 0; i < 4; i++) {
        m_i[i] = -1e30f; l_i[i] = 0.0f;
#pragma unroll
        for (int j = 0; j < 4; j++) O[i][j] = 0.0f;
    }

    const float scale = 0.125f;

    for (int kt = 0; kt <= qt; kt++) {
        const float* Kt = Kb + (size_t)kt * 64 * CC;
        const float* Vt = Vb + (size_t)kt * 64 * CC;

        __syncthreads();
#pragma unroll
        for (int i = 0; i < 4; i++) {
            int idx = tid + i * 256;
            int row = idx >> 4;
            int d4  = (idx & 15) * 4;
            float4 kv = *(const float4*)(Kt + (size_t)row * CC + d4);
            KsT[(d4 + 0) * FPAD + row] = kv.x;
            KsT[(d4 + 1) * FPAD + row] = kv.y;
            KsT[(d4 + 2) * FPAD + row] = kv.z;
            KsT[(d4 + 3) * FPAD + row] = kv.w;
            float4 vv = *(const float4*)(Vt + (size_t)row * CC + d4);
            *(float4*)&Vs[row * FPAD + d4] = vv;
        }
        __syncthreads();

        float S[4][4];
#pragma unroll
        for (int i = 0; i < 4; i++)
#pragma unroll
            for (int j = 0; j < 4; j++) S[i][j] = 0.0f;

#pragma unroll 16
        for (int d = 0; d < 64; d++) {
            float a[4], bq[4];
            *(float4*)a  = *(float4*)&QsT[d * FPAD + ty * 4];
            *(float4*)bq = *(float4*)&KsT[d * FPAD + tx * 4];
#pragma unroll
            for (int i = 0; i < 4; i++)
#pragma unroll
                for (int j = 0; j < 4; j++) S[i][j] += a[i] * bq[j];
        }

        const int qbase = qt * 64 + ty * 4;
        const int kbase = kt * 64 + tx * 4;
#pragma unroll
        for (int i = 0; i < 4; i++)
#pragma unroll
            for (int j = 0; j < 4; j++) {
                S[i][j] *= scale;
                if (kt == qt && (kbase + j) > (qbase + i)) S[i][j] = -1e30f;
            }

        float alpha[4];
#pragma unroll
        for (int i = 0; i < 4; i++) {
            float rm = fmaxf(fmaxf(S[i][0], S[i][1]), fmaxf(S[i][2], S[i][3]));
#pragma unroll
            for (int off = 8; off >= 1; off >>= 1)
                rm = fmaxf(rm, __shfl_xor_sync(0xffffffffu, rm, off));
            float mnew = fmaxf(m_i[i], rm);
            alpha[i] = __expf(m_i[i] - mnew);
            m_i[i] = mnew;

            float rs = 0.0f;
#pragma unroll
            for (int j = 0; j < 4; j++) {
                S[i][j] = __expf(S[i][j] - mnew);
                rs += S[i][j];
            }
#pragma unroll
            for (int off = 8; off >= 1; off >>= 1)
                rs += __shfl_xor_sync(0xffffffffu, rs, off);
            l_i[i] = l_i[i] * alpha[i] + rs;
#pragma unroll
            for (int j = 0; j < 4; j++) O[i][j] *= alpha[i];
        }

        __syncthreads();
#pragma unroll
        for (int i = 0; i < 4; i++)
#pragma unroll
            for (int j = 0; j < 4; j++)
                PsT[(tx * 4 + j) * FPAD + ty * 4 + i] = S[i][j];
        __syncthreads();

#pragma unroll 16
        for (int kk = 0; kk < 64; kk++) {
            float p[4], vv[4];
            *(float4*)p  = *(float4*)&PsT[kk * FPAD + ty * 4];
            *(float4*)vv = *(float4*)&Vs[kk * FPAD + tx * 4];
#pragma unroll
            for (int i = 0; i < 4; i++)
#pragma unroll
                for (int j = 0; j < 4; j++) O[i][j] += p[i] * vv[j];
        }
    }

    float* Yb = Y + ((size_t)b * TT + qt * 64) * CC + h * HD;
#pragma unroll
    for (int i = 0; i < 4; i++) {
        float inv = 1.0f / l_i[i];
        float4 o = make_float4(O[i][0] * inv, O[i][1] * inv,
                               O[i][2] * inv, O[i][3] * inv);
        *(float4*)(Yb + (size_t)(ty * 4 + i) * CC + tx * 4) = o;
    }
}

// ---------------------------------------------------------------------------
// Launcher
// ---------------------------------------------------------------------------
extern "C" void kernel_launch(void* const* d_in, const int* in_sizes, int n_in,
                              void* d_out, int out_size) {
    const float* x  = (const float*)d_in[0];
    const float* Wq = (const float*)d_in[1];
    const float* Wk = (const float*)d_in[2];
    const float* Wv = (const float*)d_in[3];
    const float* Wo = (const float*)d_in[4];
    float* out = (float*)d_out;

    float *q, *k, *v, *y;
    cudaGetSymbolAddress((void**)&q, g_Q);
    cudaGetSymbolAddress((void**)&k, g_K);
    cudaGetSymbolAddress((void**)&v, g_V);
    cudaGetSymbolAddress((void**)&y, g_Y);

    const int flash_smem = 3 * 64 * FPAD * (int)sizeof(float);
    cudaFuncSetAttribute(flash_attn, cudaFuncAttributeMaxDynamicSharedMemorySize,
                         flash_smem);
    cudaFuncSetAttribute(gemm_wmma_tf32,
                         cudaFuncAttributeMaxDynamicSharedMemorySize, GSM_BYTES);

    dim3 ggrid(CC / GBN, MTOT / GBM);       // (8, 64)
    gemm_wmma_tf32<<<ggrid, 256, GSM_BYTES>>>(x, Wq, q, MTOT, CC, CC);
    gemm_wmma_tf32<<<ggrid, 256, GSM_BYTES>>>(x, Wk, k, MTOT, CC, CC);
    gemm_wmma_tf32<<<ggrid, 256, GSM_BYTES>>>(x, Wv, v, MTOT, CC, CC);

    dim3 attn_grid(TT / 64, NH, BB);        // (32, 16, 4)
    flash_attn<<<attn_grid, 256, flash_smem>>>(q, k, v, y);

    gemm_wmma_tf32<<<ggrid, 256, GSM_BYTES>>>(y, Wo, out, MTOT, CC, CC);
}

// round 5
// speedup vs baseline: 1.9789x; 1.9789x over previous
#include <cuda_runtime.h>
#include <cuda_bf16.h>
#include <cstdint>

// Problem constants
#define BB   4
#define TT   2048
#define CC   1024
#define NH   16
#define HD   64
#define MTOT (BB * TT)        // 8192

// Scratch (device globals: no runtime allocation allowed)
__device__ float g_Q[BB * TT * CC];
__device__ float g_K[BB * TT * CC];
__device__ float g_V[BB * TT * CC];
__device__ float g_Y[BB * TT * CC];
__device__ __nv_bfloat16 g_Ahi[MTOT * CC];   // split activations (x, later y)
__device__ __nv_bfloat16 g_Alo[MTOT * CC];
__device__ __nv_bfloat16 g_Whi[4 * CC * CC]; // split weights Wq,Wk,Wv,Wo
__device__ __nv_bfloat16 g_Wlo[4 * CC * CC];

__device__ __forceinline__ uint32_t smem_u32(const void* p) {
    uint32_t a;
    asm("{ .reg .u64 t; cvta.to.shared.u64 t, %1; cvt.u32.u64 %0, t; }"
        : "=r"(a) : "l"(p));
    return a;
}
__device__ __forceinline__ void cp_async16(uint32_t dst, const void* src) {
    asm volatile("cp.async.cg.shared.global [%0], [%1], 16;"
                 :: "r"(dst), "l"(src) : "memory");
}
__device__ __forceinline__ void ldmx4(uint32_t* r, uint32_t addr) {
    asm volatile("ldmatrix.sync.aligned.m8n8.x4.shared.b16 {%0,%1,%2,%3}, [%4];"
                 : "=r"(r[0]), "=r"(r[1]), "=r"(r[2]), "=r"(r[3]) : "r"(addr));
}
__device__ __forceinline__ void mma_bf16(float* d, const uint32_t* a,
                                         const uint32_t* b) {
    asm volatile(
        "mma.sync.aligned.m16n8k16.row.col.f32.bf16.bf16.f32 "
        "{%0,%1,%2,%3}, {%4,%5,%6,%7}, {%8,%9}, {%0,%1,%2,%3};"
        : "+f"(d[0]), "+f"(d[1]), "+f"(d[2]), "+f"(d[3])
        : "r"(a[0]), "r"(a[1]), "r"(a[2]), "r"(a[3]), "r"(b[0]), "r"(b[1]));
}

// ---------------------------------------------------------------------------
// Split fp32 -> (bf16 hi, bf16 lo) so hi+lo reproduces x to ~2^-16 rel.
// ---------------------------------------------------------------------------
__global__ void split_bf16(const float* __restrict__ in,
                           __nv_bfloat16* __restrict__ hi,
                           __nv_bfloat16* __restrict__ lo, int n4) {
    int i = blockIdx.x * blockDim.x + threadIdx.x;
    if (i >= n4) return;
    float4 v = ((const float4*)in)[i];
    __nv_bfloat16 h0 = __float2bfloat16_rn(v.x);
    __nv_bfloat16 h1 = __float2bfloat16_rn(v.y);
    __nv_bfloat16 h2 = __float2bfloat16_rn(v.z);
    __nv_bfloat16 h3 = __float2bfloat16_rn(v.w);
    __nv_bfloat162 H0 = __nv_bfloat162(h0, h1), H1 = __nv_bfloat162(h2, h3);
    __nv_bfloat16 l0 = __float2bfloat16_rn(v.x - __bfloat162float(h0));
    __nv_bfloat16 l1 = __float2bfloat16_rn(v.y - __bfloat162float(h1));
    __nv_bfloat16 l2 = __float2bfloat16_rn(v.z - __bfloat162float(h2));
    __nv_bfloat16 l3 = __float2bfloat16_rn(v.w - __bfloat162float(h3));
    __nv_bfloat162 L0 = __nv_bfloat162(l0, l1), L1 = __nv_bfloat162(l2, l3);
    ((__nv_bfloat162*)hi)[i * 2 + 0] = H0;
    ((__nv_bfloat162*)hi)[i * 2 + 1] = H1;
    ((__nv_bfloat162*)lo)[i * 2 + 0] = L0;
    ((__nv_bfloat162*)lo)[i * 2 + 1] = L1;
}

// ---------------------------------------------------------------------------
// bf16x3 split GEMM (NT): C = (Ahi+Alo)(Bhi+Blo)^T minus lo*lo term.
// CTA 128x128, BK=32, 8 warps (4x2 -> 32x64/warp), mma.sync m16n8k16.
// Smem: 4 planes (Ahi,Alo,Bhi,Blo), 128 rows x 32 bf16, row stride 40 elems
// (80B -> conflict-free ldmatrix), double buffered.
// ---------------------------------------------------------------------------
#define GBM 128
#define GBN 128
#define GBK 32
#define SSTR 40                          // bf16 elems per smem row (80 B)
#define PLANE (128 * SSTR * 2)           // 10240 B
#define STAGE (4 * PLANE)                // 40960 B
#define GSM_BYTES (2 * STAGE)            // 81920 B

__global__ __launch_bounds__(256) void gemm_bf16x3(
    const __nv_bfloat16* __restrict__ Ahi, const __nv_bfloat16* __restrict__ Alo,
    const __nv_bfloat16* __restrict__ Bhi, const __nv_bfloat16* __restrict__ Blo,
    float* __restrict__ Cm, int M, int N, int K) {
    extern __shared__ char smem[];
    const uint32_t sbase = smem_u32(smem);

    const int tid  = threadIdx.x;
    const int wid  = tid >> 5;
    const int lane = tid & 31;
    const int wm   = wid >> 1;           // 0..3 -> 32-row slab
    const int wn   = wid & 1;            // 0..1 -> 64-col slab
    const int bm   = blockIdx.y * GBM;
    const int bn   = blockIdx.x * GBN;
    const int KT   = K / GBK;

    // ldmatrix lane address components
    const int rowA = lane & 15;                      // A: rows 0..15 of tile
    const int kbA  = (lane >> 4) * 8;                // k-half select
    const int nB   = ((lane >> 4) << 3) + (lane & 7);// B: n 0..15
    const int kbB  = (lane & 8);                     // 0 or 8

    float acc[2][8][4];
#pragma unroll
    for (int i = 0; i < 2; i++)
#pragma unroll
        for (int j = 0; j < 8; j++)
#pragma unroll
            for (int e = 0; e < 4; e++) acc[i][j][e] = 0.0f;

    auto load_stage = [&](int s, int kt) {
#pragma unroll
        for (int i = 0; i < 8; i++) {
            int c     = tid + i * 256;          // 0..2047
            int plane = c >> 9;                 // 0:Ahi 1:Alo 2:Bhi 3:Blo
            int r     = (c & 511) >> 2;         // 0..127
            int ch    = c & 3;                  // 16B chunk in row
            uint32_t so = sbase + s * STAGE + plane * PLANE + r * 80 + ch * 16;
            const __nv_bfloat16* src;
            if (plane == 0)      src = Ahi + (size_t)(bm + r) * K;
            else if (plane == 1) src = Alo + (size_t)(bm + r) * K;
            else if (plane == 2) src = Bhi + (size_t)(bn + r) * K;
            else                 src = Blo + (size_t)(bn + r) * K;
            cp_async16(so, src + kt * GBK + ch * 8);
        }
    };

    load_stage(0, 0);
    asm volatile("cp.async.commit_group;" ::: "memory");

    for (int kt = 0; kt < KT; kt++) {
        const int cur = kt & 1;
        if (kt + 1 < KT) load_stage(cur ^ 1, kt + 1);
        asm volatile("cp.async.commit_group;" ::: "memory");
        asm volatile("cp.async.wait_group 1;" ::: "memory");
        __syncthreads();

        const uint32_t aBase = sbase + cur * STAGE;           // Ahi plane
        const uint32_t bBase = sbase + cur * STAGE + 2 * PLANE; // Bhi plane

#pragma unroll
        for (int kk = 0; kk < 2; kk++) {
            const int ks = kk * 16;
            uint32_t ahi[2][4], alo[2][4];
#pragma unroll
            for (int i = 0; i < 2; i++) {
                uint32_t ad = aBase + ((wm * 32 + i * 16 + rowA) * SSTR + ks + kbA) * 2;
                ldmx4(ahi[i], ad);
                ldmx4(alo[i], ad + PLANE);
            }
#pragma unroll
            for (int np = 0; np < 4; np++) {
                uint32_t bd = bBase + ((wn * 64 + np * 16 + nB) * SSTR + ks + kbB) * 2;
                uint32_t bhi[4], blo[4];
                ldmx4(bhi, bd);
                ldmx4(blo, bd + PLANE);
#pragma unroll
                for (int i = 0; i < 2; i++) {
                    mma_bf16(acc[i][np * 2 + 0], ahi[i], bhi + 0);
                    mma_bf16(acc[i][np * 2 + 1], ahi[i], bhi + 2);
                    mma_bf16(acc[i][np * 2 + 0], ahi[i], blo + 0);
                    mma_bf16(acc[i][np * 2 + 1], ahi[i], blo + 2);
                    mma_bf16(acc[i][np * 2 + 0], alo[i], bhi + 0);
                    mma_bf16(acc[i][np * 2 + 1], alo[i], bhi + 2);
                }
            }
        }
        __syncthreads();
    }

    // Epilogue: mma C layout -> gmem
#pragma unroll
    for (int i = 0; i < 2; i++) {
        int row0 = bm + wm * 32 + i * 16 + (lane >> 2);
#pragma unroll
        for (int j = 0; j < 8; j++) {
            int col = bn + wn * 64 + j * 8 + (lane & 3) * 2;
            *(float2*)(Cm + (size_t)row0 * N + col) =
                make_float2(acc[i][j][0], acc[i][j][1]);
            *(float2*)(Cm + (size_t)(row0 + 8) * N + col) =
                make_float2(acc[i][j][2], acc[i][j][3]);
        }
    }
}

// ---------------------------------------------------------------------------
// Flash attention (causal, fp32) — unchanged (passing, near FFMA roofline)
// ---------------------------------------------------------------------------
#define FPAD 68

__global__ __launch_bounds__(256) void flash_attn(const float* __restrict__ Q,
                                                  const float* __restrict__ K,
                                                  const float* __restrict__ V,
                                                  float* __restrict__ Y) {
    extern __shared__ float sm[];
    float* QsT = sm;
    float* KsT = sm + 64 * FPAD;
    float* Vs  = sm + 2 * 64 * FPAD;
    float* PsT = KsT;

    const int qt  = blockIdx.x;
    const int h   = blockIdx.y;
    const int b   = blockIdx.z;
    const int tid = threadIdx.x;
    const int tx  = tid & 15;
    const int ty  = tid >> 4;

    const float* Qb = Q + ((size_t)b * TT + qt * 64) * CC + h * HD;
    const float* Kb = K + (size_t)b * TT * CC + h * HD;
    const float* Vb = V + (size_t)b * TT * CC + h * HD;

#pragma unroll
    for (int i = 0; i < 4; i++) {
        int idx = tid + i * 256;
        int row = idx >> 4;
        int d4  = (idx & 15) * 4;
        float4 v = *(const float4*)(Qb + (size_t)row * CC + d4);
        QsT[(d4 + 0) * FPAD + row] = v.x;
        QsT[(d4 + 1) * FPAD + row] = v.y;
        QsT[(d4 + 2) * FPAD + row] = v.z;
        QsT[(d4 + 3) * FPAD + row] = v.w;
    }

    float m_i[4], l_i[4], O[4][4];
#pragma unroll
    for (int i = 0; i < 4; i++) {
        m_i[i] = -1e30f; l_i[i] = 0.0f;
#pragma unroll
        for (int j = 0; j < 4; j++) O[i][j] = 0.0f;
    }

    const float scale = 0.125f;

    for (int kt = 0; kt <= qt; kt++) {
        const float* Kt = Kb + (size_t)kt * 64 * CC;
        const float* Vt = Vb + (size_t)kt * 64 * CC;

        __syncthreads();
#pragma unroll
        for (int i = 0; i < 4; i++) {
            int idx = tid + i * 256;
            int row = idx >> 4;
            int d4  = (idx & 15) * 4;
            float4 kv = *(const float4*)(Kt + (size_t)row * CC + d4);
            KsT[(d4 + 0) * FPAD + row] = kv.x;
            KsT[(d4 + 1) * FPAD + row] = kv.y;
            KsT[(d4 + 2) * FPAD + row] = kv.z;
            KsT[(d4 + 3) * FPAD + row] = kv.w;
            float4 vv = *(const float4*)(Vt + (size_t)row * CC + d4);
            *(float4*)&Vs[row * FPAD + d4] = vv;
        }
        __syncthreads();

        float S[4][4];
#pragma unroll
        for (int i = 0; i < 4; i++)
#pragma unroll
            for (int j = 0; j < 4; j++) S[i][j] = 0.0f;

#pragma unroll 16
        for (int d = 0; d < 64; d++) {
            float a[4], bq[4];
            *(float4*)a  = *(float4*)&QsT[d * FPAD + ty * 4];
            *(float4*)bq = *(float4*)&KsT[d * FPAD + tx * 4];
#pragma unroll
            for (int i = 0; i < 4; i++)
#pragma unroll
                for (int j = 0; j < 4; j++) S[i][j] += a[i] * bq[j];
        }

        const int qbase = qt * 64 + ty * 4;
        const int kbase = kt * 64 + tx * 4;
#pragma unroll
        for (int i = 0; i < 4; i++)
#pragma unroll
            for (int j = 0; j < 4; j++) {
                S[i][j] *= scale;
                if (kt == qt && (kbase + j) > (qbase + i)) S[i][j] = -1e30f;
            }

        float alpha[4];
#pragma unroll
        for (int i = 0; i < 4; i++) {
            float rm = fmaxf(fmaxf(S[i][0], S[i][1]), fmaxf(S[i][2], S[i][3]));
#pragma unroll
            for (int off = 8; off >= 1; off >>= 1)
                rm = fmaxf(rm, __shfl_xor_sync(0xffffffffu, rm, off));
            float mnew = fmaxf(m_i[i], rm);
            alpha[i] = __expf(m_i[i] - mnew);
            m_i[i] = mnew;

            float rs = 0.0f;
#pragma unroll
            for (int j = 0; j < 4; j++) {
                S[i][j] = __expf(S[i][j] - mnew);
                rs += S[i][j];
            }
#pragma unroll
            for (int off = 8; off >= 1; off >>= 1)
                rs += __shfl_xor_sync(0xffffffffu, rs, off);
            l_i[i] = l_i[i] * alpha[i] + rs;
#pragma unroll
            for (int j = 0; j < 4; j++) O[i][j] *= alpha[i];
        }

        __syncthreads();
#pragma unroll
        for (int i = 0; i < 4; i++)
#pragma unroll
            for (int j = 0; j < 4; j++)
                PsT[(tx * 4 + j) * FPAD + ty * 4 + i] = S[i][j];
        __syncthreads();

#pragma unroll 16
        for (int kk = 0; kk < 64; kk++) {
            float p[4], vv[4];
            *(float4*)p  = *(float4*)&PsT[kk * FPAD + ty * 4];
            *(float4*)vv = *(float4*)&Vs[kk * FPAD + tx * 4];
#pragma unroll
            for (int i = 0; i < 4; i++)
#pragma unroll
                for (int j = 0; j < 4; j++) O[i][j] += p[i] * vv[j];
        }
    }

    float* Yb = Y + ((size_t)b * TT + qt * 64) * CC + h * HD;
#pragma unroll
    for (int i = 0; i < 4; i++) {
        float inv = 1.0f / l_i[i];
        float4 o = make_float4(O[i][0] * inv, O[i][1] * inv,
                               O[i][2] * inv, O[i][3] * inv);
        *(float4*)(Yb + (size_t)(ty * 4 + i) * CC + tx * 4) = o;
    }
}

// ---------------------------------------------------------------------------
// Launcher
// ---------------------------------------------------------------------------
extern "C" void kernel_launch(void* const* d_in, const int* in_sizes, int n_in,
                              void* d_out, int out_size) {
    const float* x  = (const float*)d_in[0];
    const float* Wq = (const float*)d_in[1];
    const float* Wk = (const float*)d_in[2];
    const float* Wv = (const float*)d_in[3];
    const float* Wo = (const float*)d_in[4];
    float* out = (float*)d_out;

    float *q, *k, *v, *y;
    __nv_bfloat16 *ahi, *alo, *whi, *wlo;
    cudaGetSymbolAddress((void**)&q,   g_Q);
    cudaGetSymbolAddress((void**)&k,   g_K);
    cudaGetSymbolAddress((void**)&v,   g_V);
    cudaGetSymbolAddress((void**)&y,   g_Y);
    cudaGetSymbolAddress((void**)&ahi, g_Ahi);
    cudaGetSymbolAddress((void**)&alo, g_Alo);
    cudaGetSymbolAddress((void**)&whi, g_Whi);
    cudaGetSymbolAddress((void**)&wlo, g_Wlo);

    const int flash_smem = 3 * 64 * FPAD * (int)sizeof(float);
    cudaFuncSetAttribute(flash_attn, cudaFuncAttributeMaxDynamicSharedMemorySize,
                         flash_smem);
    cudaFuncSetAttribute(gemm_bf16x3,
                         cudaFuncAttributeMaxDynamicSharedMemorySize, GSM_BYTES);

    const int nX4 = (MTOT * CC) / 4;
    const int nW4 = (CC * CC) / 4;
    split_bf16<<<(nX4 + 255) / 256, 256>>>(x, ahi, alo, nX4);
    split_bf16<<<(nW4 + 255) / 256, 256>>>(Wq, whi + 0 * CC * CC, wlo + 0 * CC * CC, nW4);
    split_bf16<<<(nW4 + 255) / 256, 256>>>(Wk, whi + 1 * CC * CC, wlo + 1 * CC * CC, nW4);
    split_bf16<<<(nW4 + 255) / 256, 256>>>(Wv, whi + 2 * CC * CC, wlo + 2 * CC * CC, nW4);
    split_bf16<<<(nW4 + 255) / 256, 256>>>(Wo, whi + 3 * CC * CC, wlo + 3 * CC * CC, nW4);

    dim3 ggrid(CC / GBN, MTOT / GBM);       // (8, 64)
    gemm_bf16x3<<<ggrid, 256, GSM_BYTES>>>(ahi, alo, whi + 0 * CC * CC,
                                           wlo + 0 * CC * CC, q, MTOT, CC, CC);
    gemm_bf16x3<<<ggrid, 256, GSM_BYTES>>>(ahi, alo, whi + 1 * CC * CC,
                                           wlo + 1 * CC * CC, k, MTOT, CC, CC);
    gemm_bf16x3<<<ggrid, 256, GSM_BYTES>>>(ahi, alo, whi + 2 * CC * CC,
                                           wlo + 2 * CC * CC, v, MTOT, CC, CC);

    dim3 attn_grid(TT / 64, NH, BB);        // (32, 16, 4)
    flash_attn<<<attn_grid, 256, flash_smem>>>(q, k, v, y);

    split_bf16<<<(nX4 + 255) / 256, 256>>>(y, ahi, alo, nX4);
    gemm_bf16x3<<<ggrid, 256, GSM_BYTES>>>(ahi, alo, whi + 3 * CC * CC,
                                           wlo + 3 * CC * CC, out, MTOT, CC, CC);
}

// round 6
// speedup vs baseline: 3.3264x; 1.6809x over previous
#include <cuda_runtime.h>
#include <cuda_bf16.h>
#include <cstdint>

// Problem constants
#define BB   4
#define TT   2048
#define CC   1024
#define NH   16
#define HD   64
#define MTOT (BB * TT)        // 8192

// Scratch (device globals: no runtime allocation allowed)
__device__ __nv_bfloat16 g_Qhi[MTOT * CC];
__device__ __nv_bfloat16 g_Qlo[MTOT * CC];
__device__ __nv_bfloat16 g_Khi[MTOT * CC];
__device__ __nv_bfloat16 g_Klo[MTOT * CC];
__device__ __nv_bfloat16 g_Vhi[MTOT * CC];
__device__ __nv_bfloat16 g_Vlo[MTOT * CC];
__device__ __nv_bfloat16 g_Yhi[MTOT * CC];
__device__ __nv_bfloat16 g_Ylo[MTOT * CC];
__device__ __nv_bfloat16 g_Ahi[MTOT * CC];   // split activations x
__device__ __nv_bfloat16 g_Alo[MTOT * CC];
__device__ __nv_bfloat16 g_Whi[4 * CC * CC]; // split weights Wq,Wk,Wv,Wo
__device__ __nv_bfloat16 g_Wlo[4 * CC * CC];

__device__ __forceinline__ uint32_t smem_u32(const void* p) {
    uint32_t a;
    asm("{ .reg .u64 t; cvta.to.shared.u64 t, %1; cvt.u32.u64 %0, t; }"
        : "=r"(a) : "l"(p));
    return a;
}
__device__ __forceinline__ void cp_async16(uint32_t dst, const void* src) {
    asm volatile("cp.async.cg.shared.global [%0], [%1], 16;"
                 :: "r"(dst), "l"(src) : "memory");
}
__device__ __forceinline__ void ldmx4(uint32_t* r, uint32_t addr) {
    asm volatile("ldmatrix.sync.aligned.m8n8.x4.shared.b16 {%0,%1,%2,%3}, [%4];"
                 : "=r"(r[0]), "=r"(r[1]), "=r"(r[2]), "=r"(r[3]) : "r"(addr));
}
__device__ __forceinline__ void ldmx4t(uint32_t* r, uint32_t addr) {
    asm volatile("ldmatrix.sync.aligned.m8n8.x4.trans.shared.b16 {%0,%1,%2,%3}, [%4];"
                 : "=r"(r[0]), "=r"(r[1]), "=r"(r[2]), "=r"(r[3]) : "r"(addr));
}
__device__ __forceinline__ void mma_bf16(float* d, const uint32_t* a,
                                         const uint32_t* b) {
    asm volatile(
        "mma.sync.aligned.m16n8k16.row.col.f32.bf16.bf16.f32 "
        "{%0,%1,%2,%3}, {%4,%5,%6,%7}, {%8,%9}, {%0,%1,%2,%3};"
        : "+f"(d[0]), "+f"(d[1]), "+f"(d[2]), "+f"(d[3])
        : "r"(a[0]), "r"(a[1]), "r"(a[2]), "r"(a[3]), "r"(b[0]), "r"(b[1]));
}
// pack two floats -> bf16x2 (v0 in low half), return split hi pack + lo pack
__device__ __forceinline__ uint32_t pack_split(float v0, float v1, uint32_t& lopk) {
    __nv_bfloat16 h0 = __float2bfloat16_rn(v0), h1 = __float2bfloat16_rn(v1);
    float r0 = v0 - __bfloat162float(h0), r1 = v1 - __bfloat162float(h1);
    __nv_bfloat162 lo2(__float2bfloat16_rn(r0), __float2bfloat16_rn(r1));
    lopk = *(uint32_t*)&lo2;
    __nv_bfloat162 hi2(h0, h1);
    return *(uint32_t*)&hi2;
}

// ---------------------------------------------------------------------------
// Split fp32 -> (bf16 hi, bf16 lo)
// ---------------------------------------------------------------------------
__global__ void split_bf16(const float* __restrict__ in,
                           __nv_bfloat16* __restrict__ hi,
                           __nv_bfloat16* __restrict__ lo, int n4) {
    int i = blockIdx.x * blockDim.x + threadIdx.x;
    if (i >= n4) return;
    float4 v = ((const float4*)in)[i];
    uint32_t l0, l1, h0 = pack_split(v.x, v.y, l0), h1 = pack_split(v.z, v.w, l1);
    ((uint32_t*)hi)[i * 2 + 0] = h0;
    ((uint32_t*)hi)[i * 2 + 1] = h1;
    ((uint32_t*)lo)[i * 2 + 0] = l0;
    ((uint32_t*)lo)[i * 2 + 1] = l1;
}

// ---------------------------------------------------------------------------
// bf16x3 split GEMM (NT). Output: fp32 (Cf) or split bf16 (Chi/Clo).
// ---------------------------------------------------------------------------
#define GBM 128
#define GBN 128
#define GBK 32
#define SSTR 40
#define PLANE (128 * SSTR * 2)
#define STAGE (4 * PLANE)
#define GSM_BYTES (2 * STAGE)            // 81920 B

__global__ __launch_bounds__(256) void gemm_bf16x3(
    const __nv_bfloat16* __restrict__ Ahi, const __nv_bfloat16* __restrict__ Alo,
    const __nv_bfloat16* __restrict__ Bhi, const __nv_bfloat16* __restrict__ Blo,
    float* __restrict__ Cf, __nv_bfloat16* __restrict__ Chi,
    __nv_bfloat16* __restrict__ Clo, int M, int N, int K) {
    extern __shared__ char smem[];
    const uint32_t sbase = smem_u32(smem);

    const int tid  = threadIdx.x;
    const int wid  = tid >> 5;
    const int lane = tid & 31;
    const int wm   = wid >> 1;
    const int wn   = wid & 1;
    const int bm   = blockIdx.y * GBM;
    const int bn   = blockIdx.x * GBN;
    const int KT   = K / GBK;

    const int rowA = lane & 15;
    const int kbA  = (lane >> 4) * 8;
    const int nB   = ((lane >> 4) << 3) + (lane & 7);
    const int kbB  = (lane & 8);

    float acc[2][8][4];
#pragma unroll
    for (int i = 0; i < 2; i++)
#pragma unroll
        for (int j = 0; j < 8; j++)
#pragma unroll
            for (int e = 0; e < 4; e++) acc[i][j][e] = 0.0f;

    auto load_stage = [&](int s, int kt) {
#pragma unroll
        for (int i = 0; i < 8; i++) {
            int c     = tid + i * 256;
            int plane = c >> 9;
            int r     = (c & 511) >> 2;
            int ch    = c & 3;
            uint32_t so = sbase + s * STAGE + plane * PLANE + r * 80 + ch * 16;
            const __nv_bfloat16* src;
            if (plane == 0)      src = Ahi + (size_t)(bm + r) * K;
            else if (plane == 1) src = Alo + (size_t)(bm + r) * K;
            else if (plane == 2) src = Bhi + (size_t)(bn + r) * K;
            else                 src = Blo + (size_t)(bn + r) * K;
            cp_async16(so, src + kt * GBK + ch * 8);
        }
    };

    load_stage(0, 0);
    asm volatile("cp.async.commit_group;" ::: "memory");

    for (int kt = 0; kt < KT; kt++) {
        const int cur = kt & 1;
        if (kt + 1 < KT) load_stage(cur ^ 1, kt + 1);
        asm volatile("cp.async.commit_group;" ::: "memory");
        asm volatile("cp.async.wait_group 1;" ::: "memory");
        __syncthreads();

        const uint32_t aBase = sbase + cur * STAGE;
        const uint32_t bBase = sbase + cur * STAGE + 2 * PLANE;

#pragma unroll
        for (int kk = 0; kk < 2; kk++) {
            const int ks = kk * 16;
            uint32_t ahi[2][4], alo[2][4];
#pragma unroll
            for (int i = 0; i < 2; i++) {
                uint32_t ad = aBase + ((wm * 32 + i * 16 + rowA) * SSTR + ks + kbA) * 2;
                ldmx4(ahi[i], ad);
                ldmx4(alo[i], ad + PLANE);
            }
#pragma unroll
            for (int np = 0; np < 4; np++) {
                uint32_t bd = bBase + ((wn * 64 + np * 16 + nB) * SSTR + ks + kbB) * 2;
                uint32_t bhi[4], blo[4];
                ldmx4(bhi, bd);
                ldmx4(blo, bd + PLANE);
#pragma unroll
                for (int i = 0; i < 2; i++) {
                    mma_bf16(acc[i][np * 2 + 0], ahi[i], bhi + 0);
                    mma_bf16(acc[i][np * 2 + 1], ahi[i], bhi + 2);
                    mma_bf16(acc[i][np * 2 + 0], ahi[i], blo + 0);
                    mma_bf16(acc[i][np * 2 + 1], ahi[i], blo + 2);
                    mma_bf16(acc[i][np * 2 + 0], alo[i], bhi + 0);
                    mma_bf16(acc[i][np * 2 + 1], alo[i], bhi + 2);
                }
            }
        }
        __syncthreads();
    }

#pragma unroll
    for (int i = 0; i < 2; i++) {
        int row0 = bm + wm * 32 + i * 16 + (lane >> 2);
#pragma unroll
        for (int j = 0; j < 8; j++) {
            int col = bn + wn * 64 + j * 8 + (lane & 3) * 2;
            if (Cf) {
                *(float2*)(Cf + (size_t)row0 * N + col) =
                    make_float2(acc[i][j][0], acc[i][j][1]);
                *(float2*)(Cf + (size_t)(row0 + 8) * N + col) =
                    make_float2(acc[i][j][2], acc[i][j][3]);
            } else {
                uint32_t lp, hp;
                hp = pack_split(acc[i][j][0], acc[i][j][1], lp);
                *(uint32_t*)(Chi + (size_t)row0 * N + col) = hp;
                *(uint32_t*)(Clo + (size_t)row0 * N + col) = lp;
                hp = pack_split(acc[i][j][2], acc[i][j][3], lp);
                *(uint32_t*)(Chi + (size_t)(row0 + 8) * N + col) = hp;
                *(uint32_t*)(Clo + (size_t)(row0 + 8) * N + col) = lp;
            }
        }
    }
}

// ---------------------------------------------------------------------------
// Flash attention, causal, bf16x3 tensor-core version.
// Block = 128 q-rows x (b,h); 8 warps x 16 q-rows each; K/V tiles of 64.
// ---------------------------------------------------------------------------
#define FBQ 128
#define FBK 64
#define FSTR 72                          // bf16 elems per smem row (144 B)
#define FPL (FBK * FSTR * 2)             // 9216 B per plane
#define FSTG (4 * FPL)                   // 36864 B per stage
#define FSM_BYTES (2 * FSTG)             // 73728 B

__global__ __launch_bounds__(256) void flash_mma(
    const __nv_bfloat16* __restrict__ Qhi, const __nv_bfloat16* __restrict__ Qlo,
    const __nv_bfloat16* __restrict__ Khi, const __nv_bfloat16* __restrict__ Klo,
    const __nv_bfloat16* __restrict__ Vhi, const __nv_bfloat16* __restrict__ Vlo,
    __nv_bfloat16* __restrict__ Yhi, __nv_bfloat16* __restrict__ Ylo) {
    extern __shared__ char smem[];
    const uint32_t sbase = smem_u32(smem);
    const int tid = threadIdx.x, wid = tid >> 5, lane = tid & 31;
    const int qx = blockIdx.x, h = blockIdx.y, b = blockIdx.z;
    const int qbase = qx * FBQ;
    const int r0 = lane >> 2;
    const int c2 = (lane & 3) * 2;

    const int nB   = ((lane >> 4) << 3) + (lane & 7);
    const int kbB  = lane & 8;
    const int rowV = lane & 15;
    const int colV = (lane >> 4) * 8;

    // Q fragments (hi/lo) loaded once from global
    uint32_t qh[4][4], ql[4][4];
    {
        size_t g0 = ((size_t)(b * TT + qbase + wid * 16 + r0)) * CC + h * HD;
        size_t g1 = g0 + 8 * (size_t)CC;
#pragma unroll
        for (int ks = 0; ks < 4; ks++) {
            int col = ks * 16 + c2;
            qh[ks][0] = *(const uint32_t*)(Qhi + g0 + col);
            qh[ks][1] = *(const uint32_t*)(Qhi + g1 + col);
            qh[ks][2] = *(const uint32_t*)(Qhi + g0 + col + 8);
            qh[ks][3] = *(const uint32_t*)(Qhi + g1 + col + 8);
            ql[ks][0] = *(const uint32_t*)(Qlo + g0 + col);
            ql[ks][1] = *(const uint32_t*)(Qlo + g1 + col);
            ql[ks][2] = *(const uint32_t*)(Qlo + g0 + col + 8);
            ql[ks][3] = *(const uint32_t*)(Qlo + g1 + col + 8);
        }
    }

    float accO[8][4];
#pragma unroll
    for (int j = 0; j < 8; j++)
#pragma unroll
        for (int e = 0; e < 4; e++) accO[j][e] = 0.0f;
    float m0 = -1e30f, m1 = -1e30f, l0 = 0.0f, l1 = 0.0f;

    const int ktmax = 2 * qx + 1;

    auto load_stage = [&](int s, int kt) {
        int kbase = kt * FBK;
#pragma unroll
        for (int i = 0; i < 8; i++) {
            int c  = tid + i * 256;
            int p  = c >> 9;
            int r  = (c & 511) >> 3;
            int ch = c & 7;
            uint32_t dst = sbase + s * FSTG + p * FPL + r * 144 + ch * 16;
            size_t gi = ((size_t)(b * TT + kbase + r)) * CC + h * HD + ch * 8;
            const __nv_bfloat16* src;
            if (p == 0)      src = Khi + gi;
            else if (p == 1) src = Klo + gi;
            else if (p == 2) src = Vhi + gi;
            else             src = Vlo + gi;
            cp_async16(dst, src);
        }
    };

    load_stage(0, 0);
    asm volatile("cp.async.commit_group;" ::: "memory");

    for (int kt = 0; kt <= ktmax; kt++) {
        const int cur = kt & 1;
        if (kt < ktmax) load_stage(cur ^ 1, kt + 1);
        asm volatile("cp.async.commit_group;" ::: "memory");
        asm volatile("cp.async.wait_group 1;" ::: "memory");
        __syncthreads();

        const uint32_t kh_base = sbase + cur * FSTG;
        const uint32_t vh_base = kh_base + 2 * FPL;

        // S = Q K^T (3-term split)
        float S[8][4];
#pragma unroll
        for (int j = 0; j < 8; j++)
#pragma unroll
            for (int e = 0; e < 4; e++) S[j][e] = 0.0f;

#pragma unroll
        for (int j2 = 0; j2 < 4; j2++) {
#pragma unroll
            for (int ks = 0; ks < 4; ks++) {
                uint32_t bh[4], bl[4];
                uint32_t ad = kh_base + (uint32_t)((j2 * 16 + nB) * FSTR + ks * 16 + kbB) * 2;
                ldmx4(bh, ad);
                ldmx4(bl, ad + FPL);
                mma_bf16(S[2 * j2],     qh[ks], bh + 0);
                mma_bf16(S[2 * j2 + 1], qh[ks], bh + 2);
                mma_bf16(S[2 * j2],     qh[ks], bl + 0);
                mma_bf16(S[2 * j2 + 1], qh[ks], bl + 2);
                mma_bf16(S[2 * j2],     ql[ks], bh + 0);
                mma_bf16(S[2 * j2 + 1], ql[ks], bh + 2);
            }
        }

        // scale + causal mask (only diagonal tiles)
        const int grow0 = qbase + wid * 16 + r0;
        const bool diag = (kt >= 2 * qx);
#pragma unroll
        for (int j = 0; j < 8; j++) {
            int colb = kt * FBK + j * 8 + c2;
#pragma unroll
            for (int e = 0; e < 4; e++) {
                float v = S[j][e] * 0.125f;
                if (diag && (colb + (e & 1)) > (grow0 + ((e >> 1) << 3)))
                    v = -1e30f;
                S[j][e] = v;
            }
        }

        // online softmax
        float mx0 = -1e30f, mx1 = -1e30f;
#pragma unroll
        for (int j = 0; j < 8; j++) {
            mx0 = fmaxf(mx0, fmaxf(S[j][0], S[j][1]));
            mx1 = fmaxf(mx1, fmaxf(S[j][2], S[j][3]));
        }
        mx0 = fmaxf(mx0, __shfl_xor_sync(0xffffffffu, mx0, 1));
        mx0 = fmaxf(mx0, __shfl_xor_sync(0xffffffffu, mx0, 2));
        mx1 = fmaxf(mx1, __shfl_xor_sync(0xffffffffu, mx1, 1));
        mx1 = fmaxf(mx1, __shfl_xor_sync(0xffffffffu, mx1, 2));
        float mn0 = fmaxf(m0, mx0), mn1 = fmaxf(m1, mx1);
        float a0 = __expf(m0 - mn0), a1 = __expf(m1 - mn1);
        m0 = mn0; m1 = mn1;
        float rs0 = 0.0f, rs1 = 0.0f;
#pragma unroll
        for (int j = 0; j < 8; j++) {
            S[j][0] = __expf(S[j][0] - mn0);
            S[j][1] = __expf(S[j][1] - mn0);
            S[j][2] = __expf(S[j][2] - mn1);
            S[j][3] = __expf(S[j][3] - mn1);
            rs0 += S[j][0] + S[j][1];
            rs1 += S[j][2] + S[j][3];
        }
        rs0 += __shfl_xor_sync(0xffffffffu, rs0, 1);
        rs0 += __shfl_xor_sync(0xffffffffu, rs0, 2);
        rs1 += __shfl_xor_sync(0xffffffffu, rs1, 1);
        rs1 += __shfl_xor_sync(0xffffffffu, rs1, 2);
        l0 = l0 * a0 + rs0;
        l1 = l1 * a1 + rs1;
#pragma unroll
        for (int j = 0; j < 8; j++) {
            accO[j][0] *= a0; accO[j][1] *= a0;
            accO[j][2] *= a1; accO[j][3] *= a1;
        }

        // O += P V (3-term split), P fragments built in registers
#pragma unroll
        for (int ks = 0; ks < 4; ks++) {
            uint32_t ph[4], pl[4];
            ph[0] = pack_split(S[2 * ks][0],     S[2 * ks][1],     pl[0]);
            ph[1] = pack_split(S[2 * ks][2],     S[2 * ks][3],     pl[1]);
            ph[2] = pack_split(S[2 * ks + 1][0], S[2 * ks + 1][1], pl[2]);
            ph[3] = pack_split(S[2 * ks + 1][2], S[2 * ks + 1][3], pl[3]);
#pragma unroll
            for (int jd = 0; jd < 4; jd++) {
                uint32_t vh[4], vl[4];
                uint32_t ad = vh_base + (uint32_t)((ks * 16 + rowV) * FSTR + jd * 16 + colV) * 2;
                ldmx4t(vh, ad);
                ldmx4t(vl, ad + FPL);
                mma_bf16(accO[2 * jd],     ph, vh + 0);
                mma_bf16(accO[2 * jd + 1], ph, vh + 2);
                mma_bf16(accO[2 * jd],     ph, vl + 0);
                mma_bf16(accO[2 * jd + 1], ph, vl + 2);
                mma_bf16(accO[2 * jd],     pl, vh + 0);
                mma_bf16(accO[2 * jd + 1], pl, vh + 2);
            }
        }
        __syncthreads();
    }

    // normalize + split-write Y
    const float i0 = 1.0f / l0, i1 = 1.0f / l1;
    size_t g0 = ((size_t)(b * TT + qbase + wid * 16 + r0)) * CC + h * HD;
    size_t g1 = g0 + 8 * (size_t)CC;
#pragma unroll
    for (int j = 0; j < 8; j++) {
        int col = j * 8 + c2;
        uint32_t lp, hp;
        hp = pack_split(accO[j][0] * i0, accO[j][1] * i0, lp);
        *(uint32_t*)(Yhi + g0 + col) = hp;
        *(uint32_t*)(Ylo + g0 + col) = lp;
        hp = pack_split(accO[j][2] * i1, accO[j][3] * i1, lp);
        *(uint32_t*)(Yhi + g1 + col) = hp;
        *(uint32_t*)(Ylo + g1 + col) = lp;
    }
}

// ---------------------------------------------------------------------------
// Launcher
// ---------------------------------------------------------------------------
extern "C" void kernel_launch(void* const* d_in, const int* in_sizes, int n_in,
                              void* d_out, int out_size) {
    const float* x  = (const float*)d_in[0];
    const float* Wq = (const float*)d_in[1];
    const float* Wk = (const float*)d_in[2];
    const float* Wv = (const float*)d_in[3];
    const float* Wo = (const float*)d_in[4];
    float* out = (float*)d_out;

    __nv_bfloat16 *qhi, *qlo, *khi, *klo, *vhi, *vlo, *yhi, *ylo, *ahi, *alo, *whi, *wlo;
    cudaGetSymbolAddress((void**)&qhi, g_Qhi);
    cudaGetSymbolAddress((void**)&qlo, g_Qlo);
    cudaGetSymbolAddress((void**)&khi, g_Khi);
    cudaGetSymbolAddress((void**)&klo, g_Klo);
    cudaGetSymbolAddress((void**)&vhi, g_Vhi);
    cudaGetSymbolAddress((void**)&vlo, g_Vlo);
    cudaGetSymbolAddress((void**)&yhi, g_Yhi);
    cudaGetSymbolAddress((void**)&ylo, g_Ylo);
    cudaGetSymbolAddress((void**)&ahi, g_Ahi);
    cudaGetSymbolAddress((void**)&alo, g_Alo);
    cudaGetSymbolAddress((void**)&whi, g_Whi);
    cudaGetSymbolAddress((void**)&wlo, g_Wlo);

    cudaFuncSetAttribute(gemm_bf16x3,
                         cudaFuncAttributeMaxDynamicSharedMemorySize, GSM_BYTES);
    cudaFuncSetAttribute(flash_mma,
                         cudaFuncAttributeMaxDynamicSharedMemorySize, FSM_BYTES);

    const int nX4 = (MTOT * CC) / 4;
    const int nW4 = (CC * CC) / 4;
    split_bf16<<<(nX4 + 255) / 256, 256>>>(x, ahi, alo, nX4);
    split_bf16<<<(nW4 + 255) / 256, 256>>>(Wq, whi + 0 * CC * CC, wlo + 0 * CC * CC, nW4);
    split_bf16<<<(nW4 + 255) / 256, 256>>>(Wk, whi + 1 * CC * CC, wlo + 1 * CC * CC, nW4);
    split_bf16<<<(nW4 + 255) / 256, 256>>>(Wv, whi + 2 * CC * CC, wlo + 2 * CC * CC, nW4);
    split_bf16<<<(nW4 + 255) / 256, 256>>>(Wo, whi + 3 * CC * CC, wlo + 3 * CC * CC, nW4);

    dim3 ggrid(CC / GBN, MTOT / GBM);       // (8, 64)
    gemm_bf16x3<<<ggrid, 256, GSM_BYTES>>>(ahi, alo, whi + 0 * CC * CC,
                                           wlo + 0 * CC * CC, nullptr, qhi, qlo,
                                           MTOT, CC, CC);
    gemm_bf16x3<<<ggrid, 256, GSM_BYTES>>>(ahi, alo, whi + 1 * CC * CC,
                                           wlo + 1 * CC * CC, nullptr, khi, klo,
                                           MTOT, CC, CC);
    gemm_bf16x3<<<ggrid, 256, GSM_BYTES>>>(ahi, alo, whi + 2 * CC * CC,
                                           wlo + 2 * CC * CC, nullptr, vhi, vlo,
                                           MTOT, CC, CC);

    dim3 fgrid(TT / FBQ, NH, BB);           // (16, 16, 4)
    flash_mma<<<fgrid, 256, FSM_BYTES>>>(qhi, qlo, khi, klo, vhi, vlo, yhi, ylo);

    gemm_bf16x3<<<ggrid, 256, GSM_BYTES>>>(yhi, ylo, whi + 3 * CC * CC,
                                           wlo + 3 * CC * CC, out, nullptr, nullptr,
                                           MTOT, CC, CC);
}

// round 7
// speedup vs baseline: 4.7742x; 1.4353x over previous
#include <cuda_runtime.h>
#include <cuda_fp16.h>
#include <cstdint>

// Problem constants
#define BB   4
#define TT   2048
#define CC   1024
#define NH   16
#define HD   64
#define MTOT (BB * TT)        // 8192

// Scratch (device globals: no runtime allocation allowed)
__device__ __half g_Qhi[MTOT * CC];
__device__ __half g_Qlo[MTOT * CC];
__device__ __half g_Khi[MTOT * CC];   // plain fp16 K
__device__ __half g_Vhi[MTOT * CC];   // plain fp16 V
__device__ __half g_Yhi[MTOT * CC];
__device__ __half g_Ylo[MTOT * CC];
__device__ __half g_Ahi[MTOT * CC];   // split activations x
__device__ __half g_Alo[MTOT * CC];
__device__ __half g_Whi[4 * CC * CC]; // fp16 weights Wq,Wk,Wv,Wo

__device__ __forceinline__ uint32_t smem_u32(const void* p) {
    uint32_t a;
    asm("{ .reg .u64 t; cvta.to.shared.u64 t, %1; cvt.u32.u64 %0, t; }"
        : "=r"(a) : "l"(p));
    return a;
}
__device__ __forceinline__ void cp_async16(uint32_t dst, const void* src) {
    asm volatile("cp.async.cg.shared.global [%0], [%1], 16;"
                 :: "r"(dst), "l"(src) : "memory");
}
__device__ __forceinline__ void ldmx4(uint32_t* r, uint32_t addr) {
    asm volatile("ldmatrix.sync.aligned.m8n8.x4.shared.b16 {%0,%1,%2,%3}, [%4];"
                 : "=r"(r[0]), "=r"(r[1]), "=r"(r[2]), "=r"(r[3]) : "r"(addr));
}
__device__ __forceinline__ void ldmx4t(uint32_t* r, uint32_t addr) {
    asm volatile("ldmatrix.sync.aligned.m8n8.x4.trans.shared.b16 {%0,%1,%2,%3}, [%4];"
                 : "=r"(r[0]), "=r"(r[1]), "=r"(r[2]), "=r"(r[3]) : "r"(addr));
}
__device__ __forceinline__ void mma_fp16(float* d, const uint32_t* a,
                                         const uint32_t* b) {
    asm volatile(
        "mma.sync.aligned.m16n8k16.row.col.f32.f16.f16.f32 "
        "{%0,%1,%2,%3}, {%4,%5,%6,%7}, {%8,%9}, {%0,%1,%2,%3};"
        : "+f"(d[0]), "+f"(d[1]), "+f"(d[2]), "+f"(d[3])
        : "r"(a[0]), "r"(a[1]), "r"(a[2]), "r"(a[3]), "r"(b[0]), "r"(b[1]));
}
__device__ __forceinline__ uint32_t pack_h2(float v0, float v1) {
    __half2 h(__float2half_rn(v0), __float2half_rn(v1));
    return *(uint32_t*)&h;
}
// split pack: hi pack returned, lo pack via ref
__device__ __forceinline__ uint32_t pack_split_h(float v0, float v1, uint32_t& lopk) {
    __half h0 = __float2half_rn(v0), h1 = __float2half_rn(v1);
    lopk = pack_h2(v0 - __half2float(h0), v1 - __half2float(h1));
    __half2 hi2(h0, h1);
    return *(uint32_t*)&hi2;
}

// ---------------------------------------------------------------------------
// Split fp32 -> (fp16 hi, fp16 lo)
// ---------------------------------------------------------------------------
__global__ void split_fp16(const float* __restrict__ in,
                           __half* __restrict__ hi, __half* __restrict__ lo,
                           int n4) {
    int i = blockIdx.x * blockDim.x + threadIdx.x;
    if (i >= n4) return;
    float4 v = ((const float4*)in)[i];
    uint32_t l0, l1;
    uint32_t h0 = pack_split_h(v.x, v.y, l0);
    uint32_t h1 = pack_split_h(v.z, v.w, l1);
    ((uint32_t*)hi)[i * 2 + 0] = h0;
    ((uint32_t*)hi)[i * 2 + 1] = h1;
    ((uint32_t*)lo)[i * 2 + 0] = l0;
    ((uint32_t*)lo)[i * 2 + 1] = l1;
}
__global__ void conv_fp16(const float* __restrict__ in, __half* __restrict__ out,
                          int n4) {
    int i = blockIdx.x * blockDim.x + threadIdx.x;
    if (i >= n4) return;
    float4 v = ((const float4*)in)[i];
    ((uint32_t*)out)[i * 2 + 0] = pack_h2(v.x, v.y);
    ((uint32_t*)out)[i * 2 + 1] = pack_h2(v.z, v.w);
}

// ---------------------------------------------------------------------------
// fp16x2 split GEMM (NT): C = (Ahi+Alo) @ Bh^T, Bh plain fp16.
// CTA 128x128, BK=32, 8 warps (4x2 -> 32x64/warp), 3 smem planes, dbl buffer.
// Output: fp32 (Cf) OR fp16 Chi (+ optional split Clo).
// ---------------------------------------------------------------------------
#define GBM 128
#define GBN 128
#define GBK 32
#define SSTR 40
#define PLANE (128 * SSTR * 2)          // 10240 B
#define STAGE (3 * PLANE)               // 30720 B
#define GSM_BYTES (2 * STAGE)           // 61440 B

__global__ __launch_bounds__(256) void gemm_fp16x2(
    const __half* __restrict__ Ahi, const __half* __restrict__ Alo,
    const __half* __restrict__ Bh,
    float* __restrict__ Cf, __half* __restrict__ Chi, __half* __restrict__ Clo,
    int M, int N, int K) {
    extern __shared__ char smem[];
    const uint32_t sbase = smem_u32(smem);

    const int tid  = threadIdx.x;
    const int wid  = tid >> 5;
    const int lane = tid & 31;
    const int wm   = wid >> 1;
    const int wn   = wid & 1;
    const int bm   = blockIdx.y * GBM;
    const int bn   = blockIdx.x * GBN;
    const int KT   = K / GBK;

    const int rowA = lane & 15;
    const int kbA  = (lane >> 4) * 8;
    const int nB   = ((lane >> 4) << 3) + (lane & 7);
    const int kbB  = (lane & 8);

    float acc[2][8][4];
#pragma unroll
    for (int i = 0; i < 2; i++)
#pragma unroll
        for (int j = 0; j < 8; j++)
#pragma unroll
            for (int e = 0; e < 4; e++) acc[i][j][e] = 0.0f;

    auto load_stage = [&](int s, int kt) {
#pragma unroll
        for (int i = 0; i < 6; i++) {
            int c     = tid + i * 256;          // 0..1535
            int plane = c >> 9;                 // 0:Ahi 1:Alo 2:Bh
            int r     = (c & 511) >> 2;         // 0..127
            int ch    = c & 3;
            uint32_t so = sbase + s * STAGE + plane * PLANE + r * 80 + ch * 16;
            const __half* src;
            if (plane == 0)      src = Ahi + (size_t)(bm + r) * K;
            else if (plane == 1) src = Alo + (size_t)(bm + r) * K;
            else                 src = Bh + (size_t)(bn + r) * K;
            cp_async16(so, src + kt * GBK + ch * 8);
        }
    };

    load_stage(0, 0);
    asm volatile("cp.async.commit_group;" ::: "memory");

    for (int kt = 0; kt < KT; kt++) {
        const int cur = kt & 1;
        if (kt + 1 < KT) load_stage(cur ^ 1, kt + 1);
        asm volatile("cp.async.commit_group;" ::: "memory");
        asm volatile("cp.async.wait_group 1;" ::: "memory");
        __syncthreads();

        const uint32_t aBase = sbase + cur * STAGE;
        const uint32_t bBase = aBase + 2 * PLANE;

#pragma unroll
        for (int kk = 0; kk < 2; kk++) {
            const int ks = kk * 16;
            uint32_t ahi[2][4], alo[2][4];
#pragma unroll
            for (int i = 0; i < 2; i++) {
                uint32_t ad = aBase + ((wm * 32 + i * 16 + rowA) * SSTR + ks + kbA) * 2;
                ldmx4(ahi[i], ad);
                ldmx4(alo[i], ad + PLANE);
            }
#pragma unroll
            for (int np = 0; np < 4; np++) {
                uint32_t bd = bBase + ((wn * 64 + np * 16 + nB) * SSTR + ks + kbB) * 2;
                uint32_t bh[4];
                ldmx4(bh, bd);
#pragma unroll
                for (int i = 0; i < 2; i++) {
                    mma_fp16(acc[i][np * 2 + 0], ahi[i], bh + 0);
                    mma_fp16(acc[i][np * 2 + 1], ahi[i], bh + 2);
                    mma_fp16(acc[i][np * 2 + 0], alo[i], bh + 0);
                    mma_fp16(acc[i][np * 2 + 1], alo[i], bh + 2);
                }
            }
        }
        __syncthreads();
    }

#pragma unroll
    for (int i = 0; i < 2; i++) {
        int row0 = bm + wm * 32 + i * 16 + (lane >> 2);
#pragma unroll
        for (int j = 0; j < 8; j++) {
            int col = bn + wn * 64 + j * 8 + (lane & 3) * 2;
            if (Cf) {
                *(float2*)(Cf + (size_t)row0 * N + col) =
                    make_float2(acc[i][j][0], acc[i][j][1]);
                *(float2*)(Cf + (size_t)(row0 + 8) * N + col) =
                    make_float2(acc[i][j][2], acc[i][j][3]);
            } else if (Clo) {
                uint32_t lp, hp;
                hp = pack_split_h(acc[i][j][0], acc[i][j][1], lp);
                *(uint32_t*)(Chi + (size_t)row0 * N + col) = hp;
                *(uint32_t*)(Clo + (size_t)row0 * N + col) = lp;
                hp = pack_split_h(acc[i][j][2], acc[i][j][3], lp);
                *(uint32_t*)(Chi + (size_t)(row0 + 8) * N + col) = hp;
                *(uint32_t*)(Clo + (size_t)(row0 + 8) * N + col) = lp;
            } else {
                *(uint32_t*)(Chi + (size_t)row0 * N + col) =
                    pack_h2(acc[i][j][0], acc[i][j][1]);
                *(uint32_t*)(Chi + (size_t)(row0 + 8) * N + col) =
                    pack_h2(acc[i][j][2], acc[i][j][3]);
            }
        }
    }
}

// ---------------------------------------------------------------------------
// Flash attention, causal, fp16x2 tensor-core version.
// Block = 128 q-rows x (b,h); 8 warps x 16 q-rows; K/V tiles of 64 (fp16).
// S = (Qhi+Qlo) K^T ; O += (Phi+Plo) V.
// ---------------------------------------------------------------------------
#define FBQ 128
#define FBK 64
#define FSTR 72                          // fp16 elems per smem row (144 B)
#define FPL (FBK * FSTR * 2)             // 9216 B per plane
#define FSTG (2 * FPL)                   // 18432 B per stage (K,V)
#define FSM_BYTES (2 * FSTG)             // 36864 B

__global__ __launch_bounds__(256) void flash_mma(
    const __half* __restrict__ Qhi, const __half* __restrict__ Qlo,
    const __half* __restrict__ Kh, const __half* __restrict__ Vh,
    __half* __restrict__ Yhi, __half* __restrict__ Ylo) {
    extern __shared__ char smem[];
    const uint32_t sbase = smem_u32(smem);
    const int tid = threadIdx.x, wid = tid >> 5, lane = tid & 31;
    const int qx = blockIdx.x, h = blockIdx.y, b = blockIdx.z;
    const int qbase = qx * FBQ;
    const int r0 = lane >> 2;
    const int c2 = (lane & 3) * 2;

    const int nB   = ((lane >> 4) << 3) + (lane & 7);
    const int kbB  = lane & 8;
    const int rowV = lane & 15;
    const int colV = (lane >> 4) * 8;

    uint32_t qh[4][4], ql[4][4];
    {
        size_t g0 = ((size_t)(b * TT + qbase + wid * 16 + r0)) * CC + h * HD;
        size_t g1 = g0 + 8 * (size_t)CC;
#pragma unroll
        for (int ks = 0; ks < 4; ks++) {
            int col = ks * 16 + c2;
            qh[ks][0] = *(const uint32_t*)(Qhi + g0 + col);
            qh[ks][1] = *(const uint32_t*)(Qhi + g1 + col);
            qh[ks][2] = *(const uint32_t*)(Qhi + g0 + col + 8);
            qh[ks][3] = *(const uint32_t*)(Qhi + g1 + col + 8);
            ql[ks][0] = *(const uint32_t*)(Qlo + g0 + col);
            ql[ks][1] = *(const uint32_t*)(Qlo + g1 + col);
            ql[ks][2] = *(const uint32_t*)(Qlo + g0 + col + 8);
            ql[ks][3] = *(const uint32_t*)(Qlo + g1 + col + 8);
        }
    }

    float accO[8][4];
#pragma unroll
    for (int j = 0; j < 8; j++)
#pragma unroll
        for (int e = 0; e < 4; e++) accO[j][e] = 0.0f;
    float m0 = -1e30f, m1 = -1e30f, l0 = 0.0f, l1 = 0.0f;

    const int ktmax = 2 * qx + 1;

    auto load_stage = [&](int s, int kt) {
        int kbase = kt * FBK;
#pragma unroll
        for (int i = 0; i < 4; i++) {
            int c  = tid + i * 256;            // 0..1023
            int p  = c >> 9;                   // 0:K 1:V
            int r  = (c & 511) >> 3;
            int ch = c & 7;
            uint32_t dst = sbase + s * FSTG + p * FPL + r * 144 + ch * 16;
            size_t gi = ((size_t)(b * TT + kbase + r)) * CC + h * HD + ch * 8;
            cp_async16(dst, (p == 0 ? Kh : Vh) + gi);
        }
    };

    load_stage(0, 0);
    asm volatile("cp.async.commit_group;" ::: "memory");

    for (int kt = 0; kt <= ktmax; kt++) {
        const int cur = kt & 1;
        if (kt < ktmax) load_stage(cur ^ 1, kt + 1);
        asm volatile("cp.async.commit_group;" ::: "memory");
        asm volatile("cp.async.wait_group 1;" ::: "memory");
        __syncthreads();

        const uint32_t kh_base = sbase + cur * FSTG;
        const uint32_t vh_base = kh_base + FPL;

        float S[8][4];
#pragma unroll
        for (int j = 0; j < 8; j++)
#pragma unroll
            for (int e = 0; e < 4; e++) S[j][e] = 0.0f;

#pragma unroll
        for (int j2 = 0; j2 < 4; j2++) {
#pragma unroll
            for (int ks = 0; ks < 4; ks++) {
                uint32_t bh[4];
                uint32_t ad = kh_base + (uint32_t)((j2 * 16 + nB) * FSTR + ks * 16 + kbB) * 2;
                ldmx4(bh, ad);
                mma_fp16(S[2 * j2],     qh[ks], bh + 0);
                mma_fp16(S[2 * j2 + 1], qh[ks], bh + 2);
                mma_fp16(S[2 * j2],     ql[ks], bh + 0);
                mma_fp16(S[2 * j2 + 1], ql[ks], bh + 2);
            }
        }

        const int grow0 = qbase + wid * 16 + r0;
        const bool diag = (kt >= 2 * qx);
#pragma unroll
        for (int j = 0; j < 8; j++) {
            int colb = kt * FBK + j * 8 + c2;
#pragma unroll
            for (int e = 0; e < 4; e++) {
                float v = S[j][e] * 0.125f;
                if (diag && (colb + (e & 1)) > (grow0 + ((e >> 1) << 3)))
                    v = -1e30f;
                S[j][e] = v;
            }
        }

        float mx0 = -1e30f, mx1 = -1e30f;
#pragma unroll
        for (int j = 0; j < 8; j++) {
            mx0 = fmaxf(mx0, fmaxf(S[j][0], S[j][1]));
            mx1 = fmaxf(mx1, fmaxf(S[j][2], S[j][3]));
        }
        mx0 = fmaxf(mx0, __shfl_xor_sync(0xffffffffu, mx0, 1));
        mx0 = fmaxf(mx0, __shfl_xor_sync(0xffffffffu, mx0, 2));
        mx1 = fmaxf(mx1, __shfl_xor_sync(0xffffffffu, mx1, 1));
        mx1 = fmaxf(mx1, __shfl_xor_sync(0xffffffffu, mx1, 2));
        float mn0 = fmaxf(m0, mx0), mn1 = fmaxf(m1, mx1);
        float a0 = __expf(m0 - mn0), a1 = __expf(m1 - mn1);
        m0 = mn0; m1 = mn1;
        float rs0 = 0.0f, rs1 = 0.0f;
#pragma unroll
        for (int j = 0; j < 8; j++) {
            S[j][0] = __expf(S[j][0] - mn0);
            S[j][1] = __expf(S[j][1] - mn0);
            S[j][2] = __expf(S[j][2] - mn1);
            S[j][3] = __expf(S[j][3] - mn1);
            rs0 += S[j][0] + S[j][1];
            rs1 += S[j][2] + S[j][3];
        }
        rs0 += __shfl_xor_sync(0xffffffffu, rs0, 1);
        rs0 += __shfl_xor_sync(0xffffffffu, rs0, 2);
        rs1 += __shfl_xor_sync(0xffffffffu, rs1, 1);
        rs1 += __shfl_xor_sync(0xffffffffu, rs1, 2);
        l0 = l0 * a0 + rs0;
        l1 = l1 * a1 + rs1;
#pragma unroll
        for (int j = 0; j < 8; j++) {
            accO[j][0] *= a0; accO[j][1] *= a0;
            accO[j][2] *= a1; accO[j][3] *= a1;
        }

#pragma unroll
        for (int ks = 0; ks < 4; ks++) {
            uint32_t ph[4], pl[4];
            ph[0] = pack_split_h(S[2 * ks][0],     S[2 * ks][1],     pl[0]);
            ph[1] = pack_split_h(S[2 * ks][2],     S[2 * ks][3],     pl[1]);
            ph[2] = pack_split_h(S[2 * ks + 1][0], S[2 * ks + 1][1], pl[2]);
            ph[3] = pack_split_h(S[2 * ks + 1][2], S[2 * ks + 1][3], pl[3]);
#pragma unroll
            for (int jd = 0; jd < 4; jd++) {
                uint32_t vh[4];
                uint32_t ad = vh_base + (uint32_t)((ks * 16 + rowV) * FSTR + jd * 16 + colV) * 2;
                ldmx4t(vh, ad);
                mma_fp16(accO[2 * jd],     ph, vh + 0);
                mma_fp16(accO[2 * jd + 1], ph, vh + 2);
                mma_fp16(accO[2 * jd],     pl, vh + 0);
                mma_fp16(accO[2 * jd + 1], pl, vh + 2);
            }
        }
        __syncthreads();
    }

    const float i0 = 1.0f / l0, i1 = 1.0f / l1;
    size_t g0 = ((size_t)(b * TT + qbase + wid * 16 + r0)) * CC + h * HD;
    size_t g1 = g0 + 8 * (size_t)CC;
#pragma unroll
    for (int j = 0; j < 8; j++) {
        int col = j * 8 + c2;
        uint32_t lp, hp;
        hp = pack_split_h(accO[j][0] * i0, accO[j][1] * i0, lp);
        *(uint32_t*)(Yhi + g0 + col) = hp;
        *(uint32_t*)(Ylo + g0 + col) = lp;
        hp = pack_split_h(accO[j][2] * i1, accO[j][3] * i1, lp);
        *(uint32_t*)(Yhi + g1 + col) = hp;
        *(uint32_t*)(Ylo + g1 + col) = lp;
    }
}

// ---------------------------------------------------------------------------
// Launcher
// ---------------------------------------------------------------------------
extern "C" void kernel_launch(void* const* d_in, const int* in_sizes, int n_in,
                              void* d_out, int out_size) {
    const float* x  = (const float*)d_in[0];
    const float* Wq = (const float*)d_in[1];
    const float* Wk = (const float*)d_in[2];
    const float* Wv = (const float*)d_in[3];
    const float* Wo = (const float*)d_in[4];
    float* out = (float*)d_out;

    __half *qhi, *qlo, *khi, *vhi, *yhi, *ylo, *ahi, *alo, *whi;
    cudaGetSymbolAddress((void**)&qhi, g_Qhi);
    cudaGetSymbolAddress((void**)&qlo, g_Qlo);
    cudaGetSymbolAddress((void**)&khi, g_Khi);
    cudaGetSymbolAddress((void**)&vhi, g_Vhi);
    cudaGetSymbolAddress((void**)&yhi, g_Yhi);
    cudaGetSymbolAddress((void**)&ylo, g_Ylo);
    cudaGetSymbolAddress((void**)&ahi, g_Ahi);
    cudaGetSymbolAddress((void**)&alo, g_Alo);
    cudaGetSymbolAddress((void**)&whi, g_Whi);

    cudaFuncSetAttribute(gemm_fp16x2,
                         cudaFuncAttributeMaxDynamicSharedMemorySize, GSM_BYTES);
    cudaFuncSetAttribute(flash_mma,
                         cudaFuncAttributeMaxDynamicSharedMemorySize, FSM_BYTES);

    const int nX4 = (MTOT * CC) / 4;
    const int nW4 = (CC * CC) / 4;
    split_fp16<<<(nX4 + 255) / 256, 256>>>(x, ahi, alo, nX4);
    conv_fp16<<<(nW4 + 255) / 256, 256>>>(Wq, whi + 0 * CC * CC, nW4);
    conv_fp16<<<(nW4 + 255) / 256, 256>>>(Wk, whi + 1 * CC * CC, nW4);
    conv_fp16<<<(nW4 + 255) / 256, 256>>>(Wv, whi + 2 * CC * CC, nW4);
    conv_fp16<<<(nW4 + 255) / 256, 256>>>(Wo, whi + 3 * CC * CC, nW4);

    dim3 ggrid(CC / GBN, MTOT / GBM);       // (8, 64)
    gemm_fp16x2<<<ggrid, 256, GSM_BYTES>>>(ahi, alo, whi + 0 * CC * CC,
                                           nullptr, qhi, qlo, MTOT, CC, CC);
    gemm_fp16x2<<<ggrid, 256, GSM_BYTES>>>(ahi, alo, whi + 1 * CC * CC,
                                           nullptr, khi, nullptr, MTOT, CC, CC);
    gemm_fp16x2<<<ggrid, 256, GSM_BYTES>>>(ahi, alo, whi + 2 * CC * CC,
                                           nullptr, vhi, nullptr, MTOT, CC, CC);

    dim3 fgrid(TT / FBQ, NH, BB);           // (16, 16, 4)
    flash_mma<<<fgrid, 256, FSM_BYTES>>>(qhi, qlo, khi, vhi, yhi, ylo);

    gemm_fp16x2<<<ggrid, 256, GSM_BYTES>>>(yhi, ylo, whi + 3 * CC * CC,
                                           out, nullptr, nullptr, MTOT, CC, CC);
}

// round 8
// speedup vs baseline: 5.6108x; 1.1752x over previous
#include <cuda_runtime.h>
#include <cuda_fp16.h>
#include <cstdint>

// Problem constants
#define BB   4
#define TT   2048
#define CC   1024
#define NH   16
#define HD   64
#define MTOT (BB * TT)        // 8192

// Scratch (device globals: no runtime allocation allowed)
__device__ __half g_Qhi[MTOT * CC];   // pre-scaled by 1/8
__device__ __half g_Qlo[MTOT * CC];
__device__ __half g_Khi[MTOT * CC];   // plain fp16 K
__device__ __half g_Vhi[MTOT * CC];   // plain fp16 V
__device__ __half g_Yhi[MTOT * CC];
__device__ __half g_Ylo[MTOT * CC];
__device__ __half g_Ahi[MTOT * CC];   // split activations x
__device__ __half g_Alo[MTOT * CC];
__device__ __half g_Whi[4 * CC * CC]; // fp16 weights Wq,Wk,Wv,Wo (contiguous)

__device__ __forceinline__ uint32_t smem_u32(const void* p) {
    uint32_t a;
    asm("{ .reg .u64 t; cvta.to.shared.u64 t, %1; cvt.u32.u64 %0, t; }"
        : "=r"(a) : "l"(p));
    return a;
}
__device__ __forceinline__ void cp_async16(uint32_t dst, const void* src) {
    asm volatile("cp.async.cg.shared.global [%0], [%1], 16;"
                 :: "r"(dst), "l"(src) : "memory");
}
__device__ __forceinline__ void ldmx4(uint32_t* r, uint32_t addr) {
    asm volatile("ldmatrix.sync.aligned.m8n8.x4.shared.b16 {%0,%1,%2,%3}, [%4];"
                 : "=r"(r[0]), "=r"(r[1]), "=r"(r[2]), "=r"(r[3]) : "r"(addr));
}
__device__ __forceinline__ void ldmx4t(uint32_t* r, uint32_t addr) {
    asm volatile("ldmatrix.sync.aligned.m8n8.x4.trans.shared.b16 {%0,%1,%2,%3}, [%4];"
                 : "=r"(r[0]), "=r"(r[1]), "=r"(r[2]), "=r"(r[3]) : "r"(addr));
}
__device__ __forceinline__ void mma_fp16(float* d, const uint32_t* a,
                                         const uint32_t* b) {
    asm volatile(
        "mma.sync.aligned.m16n8k16.row.col.f32.f16.f16.f32 "
        "{%0,%1,%2,%3}, {%4,%5,%6,%7}, {%8,%9}, {%0,%1,%2,%3};"
        : "+f"(d[0]), "+f"(d[1]), "+f"(d[2]), "+f"(d[3])
        : "r"(a[0]), "r"(a[1]), "r"(a[2]), "r"(a[3]), "r"(b[0]), "r"(b[1]));
}
__device__ __forceinline__ uint32_t pack_h2(float v0, float v1) {
    __half2 h(__float2half_rn(v0), __float2half_rn(v1));
    return *(uint32_t*)&h;
}
__device__ __forceinline__ uint32_t pack_split_h(float v0, float v1, uint32_t& lopk) {
    __half h0 = __float2half_rn(v0), h1 = __float2half_rn(v1);
    lopk = pack_h2(v0 - __half2float(h0), v1 - __half2float(h1));
    __half2 hi2(h0, h1);
    return *(uint32_t*)&hi2;
}

// ---------------------------------------------------------------------------
// Conversions
// ---------------------------------------------------------------------------
__global__ void split_fp16(const float* __restrict__ in,
                           __half* __restrict__ hi, __half* __restrict__ lo,
                           int n4) {
    int i = blockIdx.x * blockDim.x + threadIdx.x;
    if (i >= n4) return;
    float4 v = ((const float4*)in)[i];
    uint32_t l0, l1;
    uint32_t h0 = pack_split_h(v.x, v.y, l0);
    uint32_t h1 = pack_split_h(v.z, v.w, l1);
    ((uint32_t*)hi)[i * 2 + 0] = h0;
    ((uint32_t*)hi)[i * 2 + 1] = h1;
    ((uint32_t*)lo)[i * 2 + 0] = l0;
    ((uint32_t*)lo)[i * 2 + 1] = l1;
}
// 4 weight matrices -> one contiguous fp16 buffer, blockIdx.y selects source
__global__ void conv_fp16_4(const float* __restrict__ W0,
                            const float* __restrict__ W1,
                            const float* __restrict__ W2,
                            const float* __restrict__ W3,
                            __half* __restrict__ out, int n4) {
    int i = blockIdx.x * blockDim.x + threadIdx.x;
    if (i >= n4) return;
    const float* src = (blockIdx.y == 0) ? W0 : (blockIdx.y == 1) ? W1
                       : (blockIdx.y == 2) ? W2 : W3;
    float4 v = ((const float4*)src)[i];
    uint32_t* dst = (uint32_t*)(out + (size_t)blockIdx.y * CC * CC);
    dst[i * 2 + 0] = pack_h2(v.x, v.y);
    dst[i * 2 + 1] = pack_h2(v.z, v.w);
}

// ---------------------------------------------------------------------------
// GEMM common geometry (128x128 tile, BK=32, 8 warps 4x2)
// ---------------------------------------------------------------------------
#define GBM 128
#define GBN 128
#define GBK 32
#define SSTR 40
#define PLANE (128 * SSTR * 2)          // 10240 B
#define STAGE (3 * PLANE)               // 30720 B
#define GSM_BYTES (2 * STAGE)           // 61440 B

// Fused QKV GEMM: N = 3072 over contiguous [Wq;Wk;Wv].
// Epilogue: n-block 0 -> Q split (scaled 1/8), 1 -> K fp16, 2 -> V fp16.
__global__ __launch_bounds__(256) void gemm_qkv(
    const __half* __restrict__ Ahi, const __half* __restrict__ Alo,
    const __half* __restrict__ Bh,
    __half* __restrict__ Qhi, __half* __restrict__ Qlo,
    __half* __restrict__ Kout, __half* __restrict__ Vout) {
    extern __shared__ char smem[];
    const uint32_t sbase = smem_u32(smem);
    const int K = CC;

    const int tid  = threadIdx.x;
    const int wid  = tid >> 5;
    const int lane = tid & 31;
    const int wm   = wid >> 1;
    const int wn   = wid & 1;
    const int bm   = blockIdx.y * GBM;
    const int bn   = blockIdx.x * GBN;          // 0..2944
    const int KT   = K / GBK;

    const int rowA = lane & 15;
    const int kbA  = (lane >> 4) * 8;
    const int nB   = ((lane >> 4) << 3) + (lane & 7);
    const int kbB  = (lane & 8);

    float acc[2][8][4];
#pragma unroll
    for (int i = 0; i < 2; i++)
#pragma unroll
        for (int j = 0; j < 8; j++)
#pragma unroll
            for (int e = 0; e < 4; e++) acc[i][j][e] = 0.0f;

    auto load_stage = [&](int s, int kt) {
#pragma unroll
        for (int i = 0; i < 6; i++) {
            int c     = tid + i * 256;
            int plane = c >> 9;
            int r     = (c & 511) >> 2;
            int ch    = c & 3;
            uint32_t so = sbase + s * STAGE + plane * PLANE + r * 80 + ch * 16;
            const __half* src;
            if (plane == 0)      src = Ahi + (size_t)(bm + r) * K;
            else if (plane == 1) src = Alo + (size_t)(bm + r) * K;
            else                 src = Bh + (size_t)(bn + r) * K;
            cp_async16(so, src + kt * GBK + ch * 8);
        }
    };

    load_stage(0, 0);
    asm volatile("cp.async.commit_group;" ::: "memory");

    for (int kt = 0; kt < KT; kt++) {
        const int cur = kt & 1;
        if (kt + 1 < KT) load_stage(cur ^ 1, kt + 1);
        asm volatile("cp.async.commit_group;" ::: "memory");
        asm volatile("cp.async.wait_group 1;" ::: "memory");
        __syncthreads();

        const uint32_t aBase = sbase + cur * STAGE;
        const uint32_t bBase = aBase + 2 * PLANE;

#pragma unroll
        for (int kk = 0; kk < 2; kk++) {
            const int ks = kk * 16;
            uint32_t ahi[2][4], alo[2][4];
#pragma unroll
            for (int i = 0; i < 2; i++) {
                uint32_t ad = aBase + ((wm * 32 + i * 16 + rowA) * SSTR + ks + kbA) * 2;
                ldmx4(ahi[i], ad);
                ldmx4(alo[i], ad + PLANE);
            }
#pragma unroll
            for (int np = 0; np < 4; np++) {
                uint32_t bd = bBase + ((wn * 64 + np * 16 + nB) * SSTR + ks + kbB) * 2;
                uint32_t bh[4];
                ldmx4(bh, bd);
#pragma unroll
                for (int i = 0; i < 2; i++) {
                    mma_fp16(acc[i][np * 2 + 0], ahi[i], bh + 0);
                    mma_fp16(acc[i][np * 2 + 1], ahi[i], bh + 2);
                    mma_fp16(acc[i][np * 2 + 0], alo[i], bh + 0);
                    mma_fp16(acc[i][np * 2 + 1], alo[i], bh + 2);
                }
            }
        }
        __syncthreads();
    }

    const int nbsel = bn >> 10;          // 0:Q 1:K 2:V
    const int ncol0 = bn & 1023;
#pragma unroll
    for (int i = 0; i < 2; i++) {
        int row0 = bm + wm * 32 + i * 16 + (lane >> 2);
#pragma unroll
        for (int j = 0; j < 8; j++) {
            int col = ncol0 + wn * 64 + j * 8 + (lane & 3) * 2;
            size_t o0 = (size_t)row0 * CC + col;
            size_t o1 = (size_t)(row0 + 8) * CC + col;
            if (nbsel == 0) {
                uint32_t lp, hp;
                hp = pack_split_h(acc[i][j][0] * 0.125f, acc[i][j][1] * 0.125f, lp);
                *(uint32_t*)(Qhi + o0) = hp;
                *(uint32_t*)(Qlo + o0) = lp;
                hp = pack_split_h(acc[i][j][2] * 0.125f, acc[i][j][3] * 0.125f, lp);
                *(uint32_t*)(Qhi + o1) = hp;
                *(uint32_t*)(Qlo + o1) = lp;
            } else if (nbsel == 1) {
                *(uint32_t*)(Kout + o0) = pack_h2(acc[i][j][0], acc[i][j][1]);
                *(uint32_t*)(Kout + o1) = pack_h2(acc[i][j][2], acc[i][j][3]);
            } else {
                *(uint32_t*)(Vout + o0) = pack_h2(acc[i][j][0], acc[i][j][1]);
                *(uint32_t*)(Vout + o1) = pack_h2(acc[i][j][2], acc[i][j][3]);
            }
        }
    }
}

// Output GEMM: out_fp32 = (Yhi+Ylo) @ Wo^T
__global__ __launch_bounds__(256) void gemm_out(
    const __half* __restrict__ Ahi, const __half* __restrict__ Alo,
    const __half* __restrict__ Bh, float* __restrict__ Cf) {
    extern __shared__ char smem[];
    const uint32_t sbase = smem_u32(smem);
    const int K = CC, N = CC;

    const int tid  = threadIdx.x;
    const int wid  = tid >> 5;
    const int lane = tid & 31;
    const int wm   = wid >> 1;
    const int wn   = wid & 1;
    const int bm   = blockIdx.y * GBM;
    const int bn   = blockIdx.x * GBN;
    const int KT   = K / GBK;

    const int rowA = lane & 15;
    const int kbA  = (lane >> 4) * 8;
    const int nB   = ((lane >> 4) << 3) + (lane & 7);
    const int kbB  = (lane & 8);

    float acc[2][8][4];
#pragma unroll
    for (int i = 0; i < 2; i++)
#pragma unroll
        for (int j = 0; j < 8; j++)
#pragma unroll
            for (int e = 0; e < 4; e++) acc[i][j][e] = 0.0f;

    auto load_stage = [&](int s, int kt) {
#pragma unroll
        for (int i = 0; i < 6; i++) {
            int c     = tid + i * 256;
            int plane = c >> 9;
            int r     = (c & 511) >> 2;
            int ch    = c & 3;
            uint32_t so = sbase + s * STAGE + plane * PLANE + r * 80 + ch * 16;
            const __half* src;
            if (plane == 0)      src = Ahi + (size_t)(bm + r) * K;
            else if (plane == 1) src = Alo + (size_t)(bm + r) * K;
            else                 src = Bh + (size_t)(bn + r) * K;
            cp_async16(so, src + kt * GBK + ch * 8);
        }
    };

    load_stage(0, 0);
    asm volatile("cp.async.commit_group;" ::: "memory");

    for (int kt = 0; kt < KT; kt++) {
        const int cur = kt & 1;
        if (kt + 1 < KT) load_stage(cur ^ 1, kt + 1);
        asm volatile("cp.async.commit_group;" ::: "memory");
        asm volatile("cp.async.wait_group 1;" ::: "memory");
        __syncthreads();

        const uint32_t aBase = sbase + cur * STAGE;
        const uint32_t bBase = aBase + 2 * PLANE;

#pragma unroll
        for (int kk = 0; kk < 2; kk++) {
            const int ks = kk * 16;
            uint32_t ahi[2][4], alo[2][4];
#pragma unroll
            for (int i = 0; i < 2; i++) {
                uint32_t ad = aBase + ((wm * 32 + i * 16 + rowA) * SSTR + ks + kbA) * 2;
                ldmx4(ahi[i], ad);
                ldmx4(alo[i], ad + PLANE);
            }
#pragma unroll
            for (int np = 0; np < 4; np++) {
                uint32_t bd = bBase + ((wn * 64 + np * 16 + nB) * SSTR + ks + kbB) * 2;
                uint32_t bh[4];
                ldmx4(bh, bd);
#pragma unroll
                for (int i = 0; i < 2; i++) {
                    mma_fp16(acc[i][np * 2 + 0], ahi[i], bh + 0);
                    mma_fp16(acc[i][np * 2 + 1], ahi[i], bh + 2);
                    mma_fp16(acc[i][np * 2 + 0], alo[i], bh + 0);
                    mma_fp16(acc[i][np * 2 + 1], alo[i], bh + 2);
                }
            }
        }
        __syncthreads();
    }

#pragma unroll
    for (int i = 0; i < 2; i++) {
        int row0 = bm + wm * 32 + i * 16 + (lane >> 2);
#pragma unroll
        for (int j = 0; j < 8; j++) {
            int col = bn + wn * 64 + j * 8 + (lane & 3) * 2;
            *(float2*)(Cf + (size_t)row0 * N + col) =
                make_float2(acc[i][j][0], acc[i][j][1]);
            *(float2*)(Cf + (size_t)(row0 + 8) * N + col) =
                make_float2(acc[i][j][2], acc[i][j][3]);
        }
    }
}

// ---------------------------------------------------------------------------
// Flash attention, causal, fp16x2. FBQ=128 q-rows, FBK=128 kv tile.
// Q pre-scaled by 1/8 at projection. 8 warps x 16 q-rows.
// ---------------------------------------------------------------------------
#define FBQ 128
#define FBK 128
#define FSTR 72                          // fp16 elems per smem row (144 B)
#define FPL (FBK * FSTR * 2)             // 18432 B per plane (128 rows x 144B)
#define FSTG (2 * FPL)                   // 36864 B per stage (K,V)
#define FSM_BYTES (2 * FSTG)             // 73728 B

__global__ __launch_bounds__(256) void flash_mma(
    const __half* __restrict__ Qhi, const __half* __restrict__ Qlo,
    const __half* __restrict__ Kh, const __half* __restrict__ Vh,
    __half* __restrict__ Yhi, __half* __restrict__ Ylo) {
    extern __shared__ char smem[];
    const uint32_t sbase = smem_u32(smem);
    const int tid = threadIdx.x, wid = tid >> 5, lane = tid & 31;
    const int qx = blockIdx.x, h = blockIdx.y, b = blockIdx.z;
    const int qbase = qx * FBQ;
    const int r0 = lane >> 2;
    const int c2 = (lane & 3) * 2;

    const int nB   = ((lane >> 4) << 3) + (lane & 7);
    const int kbB  = lane & 8;
    const int rowV = lane & 15;
    const int colV = (lane >> 4) * 8;

    uint32_t qh[4][4], ql[4][4];
    {
        size_t g0 = ((size_t)(b * TT + qbase + wid * 16 + r0)) * CC + h * HD;
        size_t g1 = g0 + 8 * (size_t)CC;
#pragma unroll
        for (int ks = 0; ks < 4; ks++) {
            int col = ks * 16 + c2;
            qh[ks][0] = *(const uint32_t*)(Qhi + g0 + col);
            qh[ks][1] = *(const uint32_t*)(Qhi + g1 + col);
            qh[ks][2] = *(const uint32_t*)(Qhi + g0 + col + 8);
            qh[ks][3] = *(const uint32_t*)(Qhi + g1 + col + 8);
            ql[ks][0] = *(const uint32_t*)(Qlo + g0 + col);
            ql[ks][1] = *(const uint32_t*)(Qlo + g1 + col);
            ql[ks][2] = *(const uint32_t*)(Qlo + g0 + col + 8);
            ql[ks][3] = *(const uint32_t*)(Qlo + g1 + col + 8);
        }
    }

    float accO[8][4];
#pragma unroll
    for (int j = 0; j < 8; j++)
#pragma unroll
        for (int e = 0; e < 4; e++) accO[j][e] = 0.0f;
    float m0 = -1e30f, m1 = -1e30f, l0 = 0.0f, l1 = 0.0f;

    const int ktmax = qx;

    auto load_stage = [&](int s, int kt) {
        int kbase = kt * FBK;
#pragma unroll
        for (int i = 0; i < 8; i++) {
            int c  = tid + i * 256;            // 0..2047
            int p  = c >> 10;                  // 0:K 1:V
            int r  = (c & 1023) >> 3;          // 0..127
            int ch = c & 7;
            uint32_t dst = sbase + s * FSTG + p * FPL + r * 144 + ch * 16;
            size_t gi = ((size_t)(b * TT + kbase + r)) * CC + h * HD + ch * 8;
            cp_async16(dst, (p == 0 ? Kh : Vh) + gi);
        }
    };

    load_stage(0, 0);
    asm volatile("cp.async.commit_group;" ::: "memory");

    for (int kt = 0; kt <= ktmax; kt++) {
        const int cur = kt & 1;
        if (kt < ktmax) load_stage(cur ^ 1, kt + 1);
        asm volatile("cp.async.commit_group;" ::: "memory");
        asm volatile("cp.async.wait_group 1;" ::: "memory");
        __syncthreads();

        const uint32_t kh_base = sbase + cur * FSTG;
        const uint32_t vh_base = kh_base + FPL;

        float S[16][4];
#pragma unroll
        for (int j = 0; j < 16; j++)
#pragma unroll
            for (int e = 0; e < 4; e++) S[j][e] = 0.0f;

#pragma unroll
        for (int j2 = 0; j2 < 8; j2++) {
#pragma unroll
            for (int ks = 0; ks < 4; ks++) {
                uint32_t bh[4];
                uint32_t ad = kh_base + (uint32_t)((j2 * 16 + nB) * FSTR + ks * 16 + kbB) * 2;
                ldmx4(bh, ad);
                mma_fp16(S[2 * j2],     qh[ks], bh + 0);
                mma_fp16(S[2 * j2 + 1], qh[ks], bh + 2);
                mma_fp16(S[2 * j2],     ql[ks], bh + 0);
                mma_fp16(S[2 * j2 + 1], ql[ks], bh + 2);
            }
        }

        // causal mask (only diagonal tile kt == qx); Q pre-scaled so S final
        const int grow0 = qbase + wid * 16 + r0;
        if (kt == ktmax) {
#pragma unroll
            for (int j = 0; j < 16; j++) {
                int colb = kt * FBK + j * 8 + c2;
#pragma unroll
                for (int e = 0; e < 4; e++) {
                    if ((colb + (e & 1)) > (grow0 + ((e >> 1) << 3)))
                        S[j][e] = -1e30f;
                }
            }
        }

        float mx0 = -1e30f, mx1 = -1e30f;
#pragma unroll
        for (int j = 0; j < 16; j++) {
            mx0 = fmaxf(mx0, fmaxf(S[j][0], S[j][1]));
            mx1 = fmaxf(mx1, fmaxf(S[j][2], S[j][3]));
        }
        mx0 = fmaxf(mx0, __shfl_xor_sync(0xffffffffu, mx0, 1));
        mx0 = fmaxf(mx0, __shfl_xor_sync(0xffffffffu, mx0, 2));
        mx1 = fmaxf(mx1, __shfl_xor_sync(0xffffffffu, mx1, 1));
        mx1 = fmaxf(mx1, __shfl_xor_sync(0xffffffffu, mx1, 2));
        float mn0 = fmaxf(m0, mx0), mn1 = fmaxf(m1, mx1);
        float a0 = __expf(m0 - mn0), a1 = __expf(m1 - mn1);
        m0 = mn0; m1 = mn1;
        float rs0 = 0.0f, rs1 = 0.0f;
#pragma unroll
        for (int j = 0; j < 16; j++) {
            S[j][0] = __expf(S[j][0] - mn0);
            S[j][1] = __expf(S[j][1] - mn0);
            S[j][2] = __expf(S[j][2] - mn1);
            S[j][3] = __expf(S[j][3] - mn1);
            rs0 += S[j][0] + S[j][1];
            rs1 += S[j][2] + S[j][3];
        }
        rs0 += __shfl_xor_sync(0xffffffffu, rs0, 1);
        rs0 += __shfl_xor_sync(0xffffffffu, rs0, 2);
        rs1 += __shfl_xor_sync(0xffffffffu, rs1, 1);
        rs1 += __shfl_xor_sync(0xffffffffu, rs1, 2);
        l0 = l0 * a0 + rs0;
        l1 = l1 * a1 + rs1;
#pragma unroll
        for (int j = 0; j < 8; j++) {
            accO[j][0] *= a0; accO[j][1] *= a0;
            accO[j][2] *= a1; accO[j][3] *= a1;
        }

#pragma unroll
        for (int ks = 0; ks < 8; ks++) {
            uint32_t ph[4], pl[4];
            ph[0] = pack_split_h(S[2 * ks][0],     S[2 * ks][1],     pl[0]);
            ph[1] = pack_split_h(S[2 * ks][2],     S[2 * ks][3],     pl[1]);
            ph[2] = pack_split_h(S[2 * ks + 1][0], S[2 * ks + 1][1], pl[2]);
            ph[3] = pack_split_h(S[2 * ks + 1][2], S[2 * ks + 1][3], pl[3]);
#pragma unroll
            for (int jd = 0; jd < 4; jd++) {
                uint32_t vh[4];
                uint32_t ad = vh_base + (uint32_t)((ks * 16 + rowV) * FSTR + jd * 16 + colV) * 2;
                ldmx4t(vh, ad);
                mma_fp16(accO[2 * jd],     ph, vh + 0);
                mma_fp16(accO[2 * jd + 1], ph, vh + 2);
                mma_fp16(accO[2 * jd],     pl, vh + 0);
                mma_fp16(accO[2 * jd + 1], pl, vh + 2);
            }
        }
        __syncthreads();
    }

    const float i0 = 1.0f / l0, i1 = 1.0f / l1;
    size_t g0 = ((size_t)(b * TT + qbase + wid * 16 + r0)) * CC + h * HD;
    size_t g1 = g0 + 8 * (size_t)CC;
#pragma unroll
    for (int j = 0; j < 8; j++) {
        int col = j * 8 + c2;
        uint32_t lp, hp;
        hp = pack_split_h(accO[j][0] * i0, accO[j][1] * i0, lp);
        *(uint32_t*)(Yhi + g0 + col) = hp;
        *(uint32_t*)(Ylo + g0 + col) = lp;
        hp = pack_split_h(accO[j][2] * i1, accO[j][3] * i1, lp);
        *(uint32_t*)(Yhi + g1 + col) = hp;
        *(uint32_t*)(Ylo + g1 + col) = lp;
    }
}

// ---------------------------------------------------------------------------
// Launcher
// ---------------------------------------------------------------------------
extern "C" void kernel_launch(void* const* d_in, const int* in_sizes, int n_in,
                              void* d_out, int out_size) {
    const float* x  = (const float*)d_in[0];
    const float* Wq = (const float*)d_in[1];
    const float* Wk = (const float*)d_in[2];
    const float* Wv = (const float*)d_in[3];
    const float* Wo = (const float*)d_in[4];
    float* out = (float*)d_out;

    __half *qhi, *qlo, *khi, *vhi, *yhi, *ylo, *ahi, *alo, *whi;
    cudaGetSymbolAddress((void**)&qhi, g_Qhi);
    cudaGetSymbolAddress((void**)&qlo, g_Qlo);
    cudaGetSymbolAddress((void**)&khi, g_Khi);
    cudaGetSymbolAddress((void**)&vhi, g_Vhi);
    cudaGetSymbolAddress((void**)&yhi, g_Yhi);
    cudaGetSymbolAddress((void**)&ylo, g_Ylo);
    cudaGetSymbolAddress((void**)&ahi, g_Ahi);
    cudaGetSymbolAddress((void**)&alo, g_Alo);
    cudaGetSymbolAddress((void**)&whi, g_Whi);

    cudaFuncSetAttribute(gemm_qkv,
                         cudaFuncAttributeMaxDynamicSharedMemorySize, GSM_BYTES);
    cudaFuncSetAttribute(gemm_out,
                         cudaFuncAttributeMaxDynamicSharedMemorySize, GSM_BYTES);
    cudaFuncSetAttribute(flash_mma,
                         cudaFuncAttributeMaxDynamicSharedMemorySize, FSM_BYTES);

    const int nX4 = (MTOT * CC) / 4;
    const int nW4 = (CC * CC) / 4;
    split_fp16<<<(nX4 + 255) / 256, 256>>>(x, ahi, alo, nX4);
    dim3 cgrid((nW4 + 255) / 256, 4);
    conv_fp16_4<<<cgrid, 256>>>(Wq, Wk, Wv, Wo, whi, nW4);

    dim3 qkvgrid(3 * CC / GBN, MTOT / GBM);     // (24, 64) = 1536 CTAs
    gemm_qkv<<<qkvgrid, 256, GSM_BYTES>>>(ahi, alo, whi, qhi, qlo, khi, vhi);

    dim3 fgrid(TT / FBQ, NH, BB);               // (16, 16, 4)
    flash_mma<<<fgrid, 256, FSM_BYTES>>>(qhi, qlo, khi, vhi, yhi, ylo);

    dim3 ogrid(CC / GBN, MTOT / GBM);           // (8, 64)
    gemm_out<<<ogrid, 256, GSM_BYTES>>>(yhi, ylo, whi + 3 * (size_t)CC * CC, out);
}